// round 1
// baseline (speedup 1.0000x reference)
#include <cuda_runtime.h>
#include <math.h>

#define D_MODEL 1024
#define SEQ     2048
#define BATCH   4
#define NHEADS  16
#define HDIM    64
#define M_TOTAL (BATCH * SEQ)      // 8192
#define LN_EPS  1e-5f

// ---------------------------------------------------------------------------
// Scratch buffers (allocation-free rule: __device__ globals)
// ---------------------------------------------------------------------------
__device__ float g_ln [M_TOTAL * D_MODEL];
__device__ float g_q  [M_TOTAL * D_MODEL];
__device__ float g_k  [M_TOTAL * D_MODEL];
__device__ float g_v  [M_TOTAL * D_MODEL];
__device__ float g_att[M_TOTAL * D_MODEL];
__device__ float g_x1 [M_TOTAL * D_MODEL];
__device__ float g_h1 [M_TOTAL * D_MODEL];

// ---------------------------------------------------------------------------
// LayerNorm: one block per row, 256 threads, D_MODEL=1024 -> 1 float4/thread
// ---------------------------------------------------------------------------
__global__ void __launch_bounds__(256) ln_kernel(
    const float* __restrict__ x, const float* __restrict__ g,
    const float* __restrict__ b, float* __restrict__ y)
{
    __shared__ float red[16];
    const int row = blockIdx.x;
    const int tid = threadIdx.x;
    const float4 v = ((const float4*)(x + (size_t)row * D_MODEL))[tid];

    float s  = v.x + v.y + v.z + v.w;
    float ss = v.x * v.x + v.y * v.y + v.z * v.z + v.w * v.w;
    #pragma unroll
    for (int o = 16; o; o >>= 1) {
        s  += __shfl_xor_sync(0xffffffffu, s,  o);
        ss += __shfl_xor_sync(0xffffffffu, ss, o);
    }
    const int wid = tid >> 5;
    if ((tid & 31) == 0) { red[wid] = s; red[8 + wid] = ss; }
    __syncthreads();
    float S = 0.f, SS = 0.f;
    #pragma unroll
    for (int w = 0; w < 8; w++) { S += red[w]; SS += red[8 + w]; }
    const float mu   = S * (1.0f / D_MODEL);
    const float var  = SS * (1.0f / D_MODEL) - mu * mu;
    const float rstd = rsqrtf(var + LN_EPS);

    const float4 gv = ((const float4*)g)[tid];
    const float4 bv = ((const float4*)b)[tid];
    float4 o;
    o.x = (v.x - mu) * rstd * gv.x + bv.x;
    o.y = (v.y - mu) * rstd * gv.y + bv.y;
    o.z = (v.z - mu) * rstd * gv.z + bv.z;
    o.w = (v.w - mu) * rstd * gv.w + bv.w;
    ((float4*)(y + (size_t)row * D_MODEL))[tid] = o;
}

// ---------------------------------------------------------------------------
// SGEMM: C[M,N] = A[M,K] * W[N,K]^T + bias [+ReLU] [+residual]
// 128x128 block tile, BK=8, 256 threads, 8x8 per-thread microtile.
// ---------------------------------------------------------------------------
#define GBM 128
#define GBN 128
#define GBK 8

__global__ void __launch_bounds__(256, 2) gemm_kernel(
    const float* __restrict__ A, const float* __restrict__ W,
    const float* __restrict__ bias, const float* __restrict__ res,
    float* __restrict__ C, int M, int N, int K, int doRelu)
{
    __shared__ float As[GBK][GBM];
    __shared__ float Ws[GBK][GBN];

    const int tid = threadIdx.x;
    const int bm  = blockIdx.y * GBM;
    const int bn  = blockIdx.x * GBN;
    const int tr  = (tid >> 4) * 8;      // 0..120
    const int tc  = (tid & 15) * 8;      // 0..120
    const int lRow = tid >> 1;           // 0..127
    const int lCol = (tid & 1) * 4;      // 0 or 4

    const float* Ap = A + (size_t)(bm + lRow) * K + lCol;
    const float* Wp = W + (size_t)(bn + lRow) * K + lCol;

    float acc[8][8];
    #pragma unroll
    for (int i = 0; i < 8; i++)
        #pragma unroll
        for (int j = 0; j < 8; j++) acc[i][j] = 0.f;

    for (int k0 = 0; k0 < K; k0 += GBK) {
        const float4 a4 = *(const float4*)(Ap + k0);
        const float4 w4 = *(const float4*)(Wp + k0);
        __syncthreads();
        As[lCol + 0][lRow] = a4.x; As[lCol + 1][lRow] = a4.y;
        As[lCol + 2][lRow] = a4.z; As[lCol + 3][lRow] = a4.w;
        Ws[lCol + 0][lRow] = w4.x; Ws[lCol + 1][lRow] = w4.y;
        Ws[lCol + 2][lRow] = w4.z; Ws[lCol + 3][lRow] = w4.w;
        __syncthreads();
        #pragma unroll
        for (int kk = 0; kk < GBK; kk++) {
            float ra[8], rb[8];
            #pragma unroll
            for (int i = 0; i < 8; i++) ra[i] = As[kk][tr + i];
            #pragma unroll
            for (int j = 0; j < 8; j++) rb[j] = Ws[kk][tc + j];
            #pragma unroll
            for (int i = 0; i < 8; i++)
                #pragma unroll
                for (int j = 0; j < 8; j++)
                    acc[i][j] = fmaf(ra[i], rb[j], acc[i][j]);
        }
    }

    float bb[8];
    #pragma unroll
    for (int j = 0; j < 8; j++) bb[j] = bias[bn + tc + j];

    #pragma unroll
    for (int i = 0; i < 8; i++) {
        const size_t base = (size_t)(bm + tr + i) * N + bn + tc;
        #pragma unroll
        for (int j = 0; j < 8; j++) {
            float v = acc[i][j] + bb[j];
            if (doRelu) v = fmaxf(v, 0.f);
            if (res) v += res[base + j];
            C[base + j] = v;
        }
    }
}

// ---------------------------------------------------------------------------
// Flash attention (fp32): per block: one (b,h), 64 queries; loop 64-key tiles.
// 256 threads in 16x16 grid, 4x4 microtile. K stored transposed in smem so
// the hot score loads are conflict-free float4 / broadcast.
// ---------------------------------------------------------------------------
#define BQ   64
#define BKT  64
#define ASTR 68   // padded row stride (floats), 272B = 17*16 so float4 stays aligned

#define FMA4(S, qc, kv) { S[0] = fmaf(qc, kv.x, S[0]); S[1] = fmaf(qc, kv.y, S[1]); \
                          S[2] = fmaf(qc, kv.z, S[2]); S[3] = fmaf(qc, kv.w, S[3]); }

__global__ void __launch_bounds__(256) attn_kernel(
    const float* __restrict__ Q, const float* __restrict__ K,
    const float* __restrict__ V, float* __restrict__ O)
{
    extern __shared__ float sm[];
    float* Qs = sm;                       // [BQ][ASTR]   Qs[q][d]
    float* Kt = Qs + BQ  * ASTR;          // [HDIM][ASTR] Kt[d][key]
    float* Vs = Kt + HDIM * ASTR;         // [BKT][ASTR]  Vs[key][d]
    float* Ps = Vs + BKT * ASTR;          // [BQ][ASTR]   Ps[q][key]

    const int tid = threadIdx.x;
    const int bh  = blockIdx.y;
    const int b   = bh >> 4;
    const int h   = bh & 15;
    const int q0  = blockIdx.x * BQ;
    const int tr  = tid >> 4;             // 0..15
    const int tc  = tid & 15;             // 0..15
    const int r0  = tr * 4;
    const int c0  = tc * 4;
    const size_t rowBase = (size_t)b * SEQ;
    const size_t headOff = (size_t)h * HDIM;

    // Load Q tile (coalesced float4)
    for (int idx = tid; idx < BQ * (HDIM / 4); idx += 256) {
        const int q  = idx >> 4;
        const int d4 = (idx & 15) * 4;
        const float4 qv = *(const float4*)&Q[(rowBase + q0 + q) * D_MODEL + headOff + d4];
        *(float4*)&Qs[q * ASTR + d4] = qv;
    }

    float m[4], l[4], acc[4][4];
    #pragma unroll
    for (int i = 0; i < 4; i++) {
        m[i] = -INFINITY; l[i] = 0.f;
        #pragma unroll
        for (int j = 0; j < 4; j++) acc[i][j] = 0.f;
    }

    for (int kt = 0; kt < SEQ; kt += BKT) {
        __syncthreads();   // protect Kt/Vs/Ps vs previous iteration's reads
        // Load K (transposed into Kt) and V tiles
        for (int idx = tid; idx < BKT * (HDIM / 4); idx += 256) {
            const int kk = idx >> 4;
            const int d4 = (idx & 15) * 4;
            const size_t goff = (rowBase + kt + kk) * D_MODEL + headOff + d4;
            const float4 kv = *(const float4*)&K[goff];
            const float4 vv = *(const float4*)&V[goff];
            Kt[(d4 + 0) * ASTR + kk] = kv.x;
            Kt[(d4 + 1) * ASTR + kk] = kv.y;
            Kt[(d4 + 2) * ASTR + kk] = kv.z;
            Kt[(d4 + 3) * ASTR + kk] = kv.w;
            *(float4*)&Vs[kk * ASTR + d4] = vv;
        }
        __syncthreads();

        // Scores s[i][j] = sum_k Qs[r0+i][k] * Kt[k][c0+j]
        float s[4][4];
        #pragma unroll
        for (int i = 0; i < 4; i++)
            #pragma unroll
            for (int j = 0; j < 4; j++) s[i][j] = 0.f;

        #pragma unroll 4
        for (int k = 0; k < HDIM; k += 4) {
            float4 qv[4], kv[4];
            #pragma unroll
            for (int i = 0; i < 4; i++) qv[i] = *(const float4*)&Qs[(r0 + i) * ASTR + k];
            #pragma unroll
            for (int x = 0; x < 4; x++) kv[x] = *(const float4*)&Kt[(k + x) * ASTR + c0];
            #pragma unroll
            for (int i = 0; i < 4; i++) {
                FMA4(s[i], qv[i].x, kv[0]);
                FMA4(s[i], qv[i].y, kv[1]);
                FMA4(s[i], qv[i].z, kv[2]);
                FMA4(s[i], qv[i].w, kv[3]);
            }
        }

        // Online softmax per query row (16 lanes share a row)
        #pragma unroll
        for (int i = 0; i < 4; i++) {
            float mx = -INFINITY;
            #pragma unroll
            for (int j = 0; j < 4; j++) { s[i][j] *= 0.125f; mx = fmaxf(mx, s[i][j]); }
            #pragma unroll
            for (int o = 8; o; o >>= 1) mx = fmaxf(mx, __shfl_xor_sync(0xffffffffu, mx, o));
            const float mnew = fmaxf(m[i], mx);
            const float sc   = __expf(m[i] - mnew);
            m[i] = mnew;
            float rs = 0.f;
            float4 p4;
            p4.x = __expf(s[i][0] - mnew); rs += p4.x;
            p4.y = __expf(s[i][1] - mnew); rs += p4.y;
            p4.z = __expf(s[i][2] - mnew); rs += p4.z;
            p4.w = __expf(s[i][3] - mnew); rs += p4.w;
            #pragma unroll
            for (int o = 8; o; o >>= 1) rs += __shfl_xor_sync(0xffffffffu, rs, o);
            l[i] = l[i] * sc + rs;
            #pragma unroll
            for (int j = 0; j < 4; j++) acc[i][j] *= sc;
            *(float4*)&Ps[(r0 + i) * ASTR + c0] = p4;
        }
        __syncthreads();

        // acc[i][j] += sum_k Ps[r0+i][k] * Vs[k][c0+j]
        #pragma unroll 4
        for (int k = 0; k < BKT; k += 4) {
            float4 pv[4], vv[4];
            #pragma unroll
            for (int i = 0; i < 4; i++) pv[i] = *(const float4*)&Ps[(r0 + i) * ASTR + k];
            #pragma unroll
            for (int x = 0; x < 4; x++) vv[x] = *(const float4*)&Vs[(k + x) * ASTR + c0];
            #pragma unroll
            for (int i = 0; i < 4; i++) {
                FMA4(acc[i], pv[i].x, vv[0]);
                FMA4(acc[i], pv[i].y, vv[1]);
                FMA4(acc[i], pv[i].z, vv[2]);
                FMA4(acc[i], pv[i].w, vv[3]);
            }
        }
    }

    // Epilogue: divide by l, write [B,S,H,dh] (== head-major columns of [M,D])
    #pragma unroll
    for (int i = 0; i < 4; i++) {
        const float invl = 1.0f / l[i];
        float4 o;
        o.x = acc[i][0] * invl; o.y = acc[i][1] * invl;
        o.z = acc[i][2] * invl; o.w = acc[i][3] * invl;
        *(float4*)&O[(rowBase + q0 + r0 + i) * D_MODEL + headOff + c0] = o;
    }
}

// ---------------------------------------------------------------------------
// Launch
// ---------------------------------------------------------------------------
#define ATTN_SMEM ((BQ + HDIM + BKT + BQ) * ASTR * (int)sizeof(float))  // 69632 B

extern "C" void kernel_launch(void* const* d_in, const int* in_sizes, int n_in,
                              void* d_out, int out_size)
{
    const float* src = (const float*)d_in[0];
    const float* Wq  = (const float*)d_in[1];  const float* bq = (const float*)d_in[2];
    const float* Wk  = (const float*)d_in[3];  const float* bk = (const float*)d_in[4];
    const float* Wv  = (const float*)d_in[5];  const float* bv = (const float*)d_in[6];
    const float* Wo  = (const float*)d_in[7];  const float* bo = (const float*)d_in[8];
    const float* W1  = (const float*)d_in[9];  const float* b1 = (const float*)d_in[10];
    const float* W2  = (const float*)d_in[11]; const float* b2 = (const float*)d_in[12];
    const float* g1  = (const float*)d_in[13]; const float* be1 = (const float*)d_in[14];
    const float* g2  = (const float*)d_in[15]; const float* be2 = (const float*)d_in[16];
    float* out = (float*)d_out;

    float *ln, *q, *k, *v, *att, *x1, *h1;
    cudaGetSymbolAddress((void**)&ln,  g_ln);
    cudaGetSymbolAddress((void**)&q,   g_q);
    cudaGetSymbolAddress((void**)&k,   g_k);
    cudaGetSymbolAddress((void**)&v,   g_v);
    cudaGetSymbolAddress((void**)&att, g_att);
    cudaGetSymbolAddress((void**)&x1,  g_x1);
    cudaGetSymbolAddress((void**)&h1,  g_h1);

    cudaFuncSetAttribute(attn_kernel, cudaFuncAttributeMaxDynamicSharedMemorySize, ATTN_SMEM);

    const dim3 gGemm(D_MODEL / GBN, M_TOTAL / GBM);   // (8, 64)
    const dim3 gAttn(SEQ / BQ, BATCH * NHEADS);       // (32, 64)

    // x = src; ln1 = LN(x)
    ln_kernel<<<M_TOTAL, 256>>>(src, g1, be1, ln);
    // Q/K/V projections
    gemm_kernel<<<gGemm, 256>>>(ln, Wq, bq, nullptr, q, M_TOTAL, D_MODEL, D_MODEL, 0);
    gemm_kernel<<<gGemm, 256>>>(ln, Wk, bk, nullptr, k, M_TOTAL, D_MODEL, D_MODEL, 0);
    gemm_kernel<<<gGemm, 256>>>(ln, Wv, bv, nullptr, v, M_TOTAL, D_MODEL, D_MODEL, 0);
    // attention
    attn_kernel<<<gAttn, 256, ATTN_SMEM>>>(q, k, v, att);
    // x1 = src + att @ Wo^T + bo
    gemm_kernel<<<gGemm, 256>>>(att, Wo, bo, src, x1, M_TOTAL, D_MODEL, D_MODEL, 0);
    // ln2
    ln_kernel<<<M_TOTAL, 256>>>(x1, g2, be2, ln);
    // h1 = relu(ln2 @ W1^T + b1)
    gemm_kernel<<<gGemm, 256>>>(ln, W1, b1, nullptr, h1, M_TOTAL, D_MODEL, D_MODEL, 1);
    // out = x1 + h1 @ W2^T + b2
    gemm_kernel<<<gGemm, 256>>>(h1, W2, b2, x1, out, M_TOTAL, D_MODEL, D_MODEL, 0);
}

// round 3
// speedup vs baseline: 1.7054x; 1.7054x over previous
#include <cuda_runtime.h>
#include <cuda_bf16.h>
#include <math.h>
#include <stdint.h>

#define D_MODEL 1024
#define SEQ     2048
#define BATCH   4
#define NHEADS  16
#define HDIM    64
#define M_TOTAL (BATCH * SEQ)      // 8192
#define LN_EPS  1e-5f

// ---------------------------------------------------------------------------
// Scratch buffers (allocation-free rule: __device__ globals)
// ---------------------------------------------------------------------------
__device__ float g_ln [M_TOTAL * D_MODEL];
__device__ float g_q  [M_TOTAL * D_MODEL];
__device__ float g_k  [M_TOTAL * D_MODEL];
__device__ float g_v  [M_TOTAL * D_MODEL];
__device__ float g_att[M_TOTAL * D_MODEL];
__device__ float g_x1 [M_TOTAL * D_MODEL];
__device__ float g_h1 [M_TOTAL * D_MODEL];
__device__ __nv_bfloat16 g_ahi[M_TOTAL * D_MODEL];
__device__ __nv_bfloat16 g_alo[M_TOTAL * D_MODEL];
__device__ __nv_bfloat16 g_whi[D_MODEL * D_MODEL];
__device__ __nv_bfloat16 g_wlo[D_MODEL * D_MODEL];

// ---------------------------------------------------------------------------
// Portable tensor-core helpers (sm_80+ ISA only: mma.sync / ldmatrix / cp.async)
// ---------------------------------------------------------------------------
__device__ __forceinline__ uint32_t smem_u32(const void* p) {
    uint32_t a;
    asm("{ .reg .u64 t; cvta.to.shared.u64 t, %1; cvt.u32.u64 %0, t; }" : "=r"(a) : "l"(p));
    return a;
}
#define CP_ASYNC16(sa, g) \
    asm volatile("cp.async.cg.shared.global [%0], [%1], 16;" :: "r"(sa), "l"(g) : "memory")
#define CP_COMMIT() asm volatile("cp.async.commit_group;" ::: "memory")
#define CP_WAIT0()  asm volatile("cp.async.wait_group 0;" ::: "memory")
#define CP_WAIT1()  asm volatile("cp.async.wait_group 1;" ::: "memory")

__device__ __forceinline__ void ldsm4(uint32_t* r, uint32_t addr) {
    asm volatile("ldmatrix.sync.aligned.m8n8.x4.shared.b16 {%0,%1,%2,%3}, [%4];"
                 : "=r"(r[0]), "=r"(r[1]), "=r"(r[2]), "=r"(r[3]) : "r"(addr));
}
__device__ __forceinline__ void mma_bf16(float* d, const uint32_t* a, const uint32_t* b) {
    asm volatile("mma.sync.aligned.m16n8k16.row.col.f32.bf16.bf16.f32 "
                 "{%0,%1,%2,%3}, {%4,%5,%6,%7}, {%8,%9}, {%0,%1,%2,%3};"
                 : "+f"(d[0]), "+f"(d[1]), "+f"(d[2]), "+f"(d[3])
                 : "r"(a[0]), "r"(a[1]), "r"(a[2]), "r"(a[3]), "r"(b[0]), "r"(b[1]));
}

// ---------------------------------------------------------------------------
// fp32 -> bf16 hi/lo split
// ---------------------------------------------------------------------------
__global__ void __launch_bounds__(256) split_kernel(
    const float* __restrict__ x, __nv_bfloat16* __restrict__ hi,
    __nv_bfloat16* __restrict__ lo, int n4)
{
    const int i = blockIdx.x * 256 + threadIdx.x;
    if (i >= n4) return;
    const float4 v = ((const float4*)x)[i];
    __nv_bfloat16 h0 = __float2bfloat16_rn(v.x);
    __nv_bfloat16 h1 = __float2bfloat16_rn(v.y);
    __nv_bfloat16 h2 = __float2bfloat16_rn(v.z);
    __nv_bfloat16 h3 = __float2bfloat16_rn(v.w);
    __nv_bfloat16 l0 = __float2bfloat16_rn(v.x - __bfloat162float(h0));
    __nv_bfloat16 l1 = __float2bfloat16_rn(v.y - __bfloat162float(h1));
    __nv_bfloat16 l2 = __float2bfloat16_rn(v.z - __bfloat162float(h2));
    __nv_bfloat16 l3 = __float2bfloat16_rn(v.w - __bfloat162float(h3));
    ((__nv_bfloat162*)hi)[2 * i + 0] = __nv_bfloat162(h0, h1);
    ((__nv_bfloat162*)hi)[2 * i + 1] = __nv_bfloat162(h2, h3);
    ((__nv_bfloat162*)lo)[2 * i + 0] = __nv_bfloat162(l0, l1);
    ((__nv_bfloat162*)lo)[2 * i + 1] = __nv_bfloat162(l2, l3);
}

// ---------------------------------------------------------------------------
// mma.sync GEMM: C[M,1024] = A[M,1024] * W[1024,1024]^T + bias [+ReLU] [+res]
// A,W as bf16 hi/lo (bf16x3). 128x128 CTA tile, 8 warps (2x4), 64x32 warp
// tile. BK=64 (128B rows, XOR-swizzled), double-buffered cp.async.
// ---------------------------------------------------------------------------
#define TILE_B   16384                  // 128 rows x 64 bf16 x 2B
#define STAGE_B  (4 * TILE_B)           // Ahi, Alo, Whi, Wlo
#define MMG_SMEM (2 * STAGE_B)          // 131072

// swizzled byte offset of (row, 16B-chunk) inside a tile
__device__ __forceinline__ uint32_t swadr(uint32_t tbase, int row, int chunk) {
    return tbase + row * 128 + (((chunk ^ row) & 7) << 4) + ((chunk & ~7) << 4);
}

__global__ void __launch_bounds__(256, 1)
mm_gemm(const __nv_bfloat16* __restrict__ Ahi, const __nv_bfloat16* __restrict__ Alo,
        const __nv_bfloat16* __restrict__ Whi, const __nv_bfloat16* __restrict__ Wlo,
        const float* __restrict__ bias, const float* __restrict__ res,
        float* __restrict__ C, int doRelu)
{
    extern __shared__ char smem[];
    const uint32_t sb = smem_u32(smem);
    const int tid = threadIdx.x;
    const int wid = tid >> 5;
    const int lid = tid & 31;
    const int warpM = wid >> 2;          // 0..1
    const int warpN = wid & 3;           // 0..3
    const int bn = blockIdx.x * 128;
    const int bm = blockIdx.y * 128;

    const __nv_bfloat16* baseA0 = Ahi + (size_t)bm * 1024;
    const __nv_bfloat16* baseA1 = Alo + (size_t)bm * 1024;
    const __nv_bfloat16* baseW0 = Whi + (size_t)bn * 1024;
    const __nv_bfloat16* baseW1 = Wlo + (size_t)bn * 1024;

    // 4096 16B chunks per stage, 16 per thread; tile = i>>2 (compile-time)
    #define LOAD_CHUNK(stg, k0) do {                                              \
        const uint32_t _sbase = sb + (stg) * STAGE_B;                             \
        _Pragma("unroll")                                                         \
        for (int i = 0; i < 16; i++) {                                            \
            const int tile = i >> 2;                                              \
            const int idx  = (tid + i * 256) & 1023;                              \
            const int r    = idx >> 3;                                            \
            const int c8   = idx & 7;                                             \
            const __nv_bfloat16* gp =                                             \
                (tile == 0 ? baseA0 : tile == 1 ? baseA1 :                        \
                 tile == 2 ? baseW0 : baseW1) + (size_t)r * 1024 + (k0) + c8 * 8; \
            const uint32_t sa = _sbase + tile * TILE_B +                          \
                (uint32_t)(r * 128 + (((c8 ^ r) & 7) << 4));                      \
            CP_ASYNC16(sa, gp);                                                   \
        }                                                                         \
        CP_COMMIT();                                                              \
    } while (0)

    float acc[4][4][4];
    #pragma unroll
    for (int a = 0; a < 4; a++)
        #pragma unroll
        for (int b = 0; b < 4; b++)
            #pragma unroll
            for (int c = 0; c < 4; c++) acc[a][b][c] = 0.f;

    // lane address components (constant over k-chunks)
    const int aRow = warpM * 64 + (lid & 15);          // + mt*16; chunk += lid>>4
    const int aChk = lid >> 4;
    const int bRow = warpN * 32 + ((lid >= 16) ? 8 : 0) + (lid & 7);  // + pair*16
    const int bChk = (lid >> 3) & 1;

    LOAD_CHUNK(0, 0);

    #pragma unroll 1
    for (int c = 0; c < 16; c++) {
        const int s = c & 1;
        __syncthreads();                 // all warps done with buffer s from c-2
        if (c < 15) { LOAD_CHUNK(s ^ 1, (c + 1) * 64); CP_WAIT1(); }
        else        { CP_WAIT0(); }
        __syncthreads();

        const uint32_t sA0 = sb + s * STAGE_B;
        const uint32_t sA1 = sA0 + TILE_B;
        const uint32_t sW0 = sA0 + 2 * TILE_B;
        const uint32_t sW1 = sA0 + 3 * TILE_B;

        #pragma unroll
        for (int s16 = 0; s16 < 4; s16++) {
            const int kc = s16 * 2;
            // B fragments: [nt][2] for hi and lo (two x4 loads each)
            uint32_t Bh[4][2], Bl[4][2];
            #pragma unroll
            for (int pair = 0; pair < 2; pair++) {
                const int r = bRow + pair * 16;
                ldsm4(&Bh[pair * 2][0], swadr(sW0, r, kc + bChk));
                ldsm4(&Bl[pair * 2][0], swadr(sW1, r, kc + bChk));
            }
            #pragma unroll
            for (int mt = 0; mt < 4; mt++) {
                uint32_t Ah[4], Al[4];
                const int r = aRow + mt * 16;
                ldsm4(Ah, swadr(sA0, r, kc + aChk));
                ldsm4(Al, swadr(sA1, r, kc + aChk));
                #pragma unroll
                for (int nt = 0; nt < 4; nt++) {
                    mma_bf16(acc[mt][nt], Ah, Bh[nt]);
                    mma_bf16(acc[mt][nt], Ah, Bl[nt]);
                    mma_bf16(acc[mt][nt], Al, Bh[nt]);
                }
            }
        }
    }

    // Epilogue: D frag layout — d0,d1: row=l>>2, cols=(l&3)*2,(+1); d2,d3: row+8
    const int rowoff = lid >> 2;
    const int coloff = (lid & 3) * 2;
    #pragma unroll
    for (int mt = 0; mt < 4; mt++) {
        #pragma unroll
        for (int nt = 0; nt < 4; nt++) {
            const int gn = bn + warpN * 32 + nt * 8 + coloff;
            const float b0 = __ldg(&bias[gn]);
            const float b1 = __ldg(&bias[gn + 1]);
            #pragma unroll
            for (int half = 0; half < 2; half++) {
                const int gm = bm + warpM * 64 + mt * 16 + rowoff + half * 8;
                float v0 = acc[mt][nt][half * 2 + 0] + b0;
                float v1 = acc[mt][nt][half * 2 + 1] + b1;
                if (doRelu) { v0 = fmaxf(v0, 0.f); v1 = fmaxf(v1, 0.f); }
                const size_t off = (size_t)gm * 1024 + gn;
                if (res) {
                    const float2 rv = *(const float2*)&res[off];
                    v0 += rv.x; v1 += rv.y;
                }
                *(float2*)&C[off] = make_float2(v0, v1);
            }
        }
    }
}

// ---------------------------------------------------------------------------
// LayerNorm: one block per row
// ---------------------------------------------------------------------------
__global__ void __launch_bounds__(256) ln_kernel(
    const float* __restrict__ x, const float* __restrict__ g,
    const float* __restrict__ b, float* __restrict__ y)
{
    __shared__ float red[16];
    const int row = blockIdx.x;
    const int tid = threadIdx.x;
    const float4 v = ((const float4*)(x + (size_t)row * D_MODEL))[tid];

    float s  = v.x + v.y + v.z + v.w;
    float ss = v.x * v.x + v.y * v.y + v.z * v.z + v.w * v.w;
    #pragma unroll
    for (int o = 16; o; o >>= 1) {
        s  += __shfl_xor_sync(0xffffffffu, s,  o);
        ss += __shfl_xor_sync(0xffffffffu, ss, o);
    }
    const int wid = tid >> 5;
    if ((tid & 31) == 0) { red[wid] = s; red[8 + wid] = ss; }
    __syncthreads();
    float S = 0.f, SS = 0.f;
    #pragma unroll
    for (int w = 0; w < 8; w++) { S += red[w]; SS += red[8 + w]; }
    const float mu   = S * (1.0f / D_MODEL);
    const float var  = SS * (1.0f / D_MODEL) - mu * mu;
    const float rstd = rsqrtf(var + LN_EPS);

    const float4 gv = ((const float4*)g)[tid];
    const float4 bv = ((const float4*)b)[tid];
    float4 o;
    o.x = (v.x - mu) * rstd * gv.x + bv.x;
    o.y = (v.y - mu) * rstd * gv.y + bv.y;
    o.z = (v.z - mu) * rstd * gv.z + bv.z;
    o.w = (v.w - mu) * rstd * gv.w + bv.w;
    ((float4*)(y + (size_t)row * D_MODEL))[tid] = o;
}

// ---------------------------------------------------------------------------
// Flash attention (fp32), unchanged (known good)
// ---------------------------------------------------------------------------
#define BQ   64
#define BKT  64
#define ASTR 68

#define FMA4(S, qc, kv) { S[0] = fmaf(qc, kv.x, S[0]); S[1] = fmaf(qc, kv.y, S[1]); \
                          S[2] = fmaf(qc, kv.z, S[2]); S[3] = fmaf(qc, kv.w, S[3]); }

__global__ void __launch_bounds__(256) attn_kernel(
    const float* __restrict__ Q, const float* __restrict__ K,
    const float* __restrict__ V, float* __restrict__ O)
{
    extern __shared__ float sm[];
    float* Qs = sm;
    float* Kt = Qs + BQ  * ASTR;
    float* Vs = Kt + HDIM * ASTR;
    float* Ps = Vs + BKT * ASTR;

    const int tid = threadIdx.x;
    const int bh  = blockIdx.y;
    const int b   = bh >> 4;
    const int h   = bh & 15;
    const int q0  = blockIdx.x * BQ;
    const int tr  = tid >> 4;
    const int tc  = tid & 15;
    const int r0  = tr * 4;
    const int c0  = tc * 4;
    const size_t rowBase = (size_t)b * SEQ;
    const size_t headOff = (size_t)h * HDIM;

    for (int idx = tid; idx < BQ * (HDIM / 4); idx += 256) {
        const int q  = idx >> 4;
        const int d4 = (idx & 15) * 4;
        const float4 qv = *(const float4*)&Q[(rowBase + q0 + q) * D_MODEL + headOff + d4];
        *(float4*)&Qs[q * ASTR + d4] = qv;
    }

    float m[4], l[4], acc[4][4];
    #pragma unroll
    for (int i = 0; i < 4; i++) {
        m[i] = -INFINITY; l[i] = 0.f;
        #pragma unroll
        for (int j = 0; j < 4; j++) acc[i][j] = 0.f;
    }

    for (int kt = 0; kt < SEQ; kt += BKT) {
        __syncthreads();
        for (int idx = tid; idx < BKT * (HDIM / 4); idx += 256) {
            const int kk = idx >> 4;
            const int d4 = (idx & 15) * 4;
            const size_t goff = (rowBase + kt + kk) * D_MODEL + headOff + d4;
            const float4 kv = *(const float4*)&K[goff];
            const float4 vv = *(const float4*)&V[goff];
            Kt[(d4 + 0) * ASTR + kk] = kv.x;
            Kt[(d4 + 1) * ASTR + kk] = kv.y;
            Kt[(d4 + 2) * ASTR + kk] = kv.z;
            Kt[(d4 + 3) * ASTR + kk] = kv.w;
            *(float4*)&Vs[kk * ASTR + d4] = vv;
        }
        __syncthreads();

        float s[4][4];
        #pragma unroll
        for (int i = 0; i < 4; i++)
            #pragma unroll
            for (int j = 0; j < 4; j++) s[i][j] = 0.f;

        #pragma unroll 4
        for (int k = 0; k < HDIM; k += 4) {
            float4 qv[4], kv[4];
            #pragma unroll
            for (int i = 0; i < 4; i++) qv[i] = *(const float4*)&Qs[(r0 + i) * ASTR + k];
            #pragma unroll
            for (int x = 0; x < 4; x++) kv[x] = *(const float4*)&Kt[(k + x) * ASTR + c0];
            #pragma unroll
            for (int i = 0; i < 4; i++) {
                FMA4(s[i], qv[i].x, kv[0]);
                FMA4(s[i], qv[i].y, kv[1]);
                FMA4(s[i], qv[i].z, kv[2]);
                FMA4(s[i], qv[i].w, kv[3]);
            }
        }

        #pragma unroll
        for (int i = 0; i < 4; i++) {
            float mx = -INFINITY;
            #pragma unroll
            for (int j = 0; j < 4; j++) { s[i][j] *= 0.125f; mx = fmaxf(mx, s[i][j]); }
            #pragma unroll
            for (int o = 8; o; o >>= 1) mx = fmaxf(mx, __shfl_xor_sync(0xffffffffu, mx, o));
            const float mnew = fmaxf(m[i], mx);
            const float sc   = __expf(m[i] - mnew);
            m[i] = mnew;
            float rs = 0.f;
            float4 p4;
            p4.x = __expf(s[i][0] - mnew); rs += p4.x;
            p4.y = __expf(s[i][1] - mnew); rs += p4.y;
            p4.z = __expf(s[i][2] - mnew); rs += p4.z;
            p4.w = __expf(s[i][3] - mnew); rs += p4.w;
            #pragma unroll
            for (int o = 8; o; o >>= 1) rs += __shfl_xor_sync(0xffffffffu, rs, o);
            l[i] = l[i] * sc + rs;
            #pragma unroll
            for (int j = 0; j < 4; j++) acc[i][j] *= sc;
            *(float4*)&Ps[(r0 + i) * ASTR + c0] = p4;
        }
        __syncthreads();

        #pragma unroll 4
        for (int k = 0; k < BKT; k += 4) {
            float4 pv[4], vv[4];
            #pragma unroll
            for (int i = 0; i < 4; i++) pv[i] = *(const float4*)&Ps[(r0 + i) * ASTR + k];
            #pragma unroll
            for (int x = 0; x < 4; x++) vv[x] = *(const float4*)&Vs[(k + x) * ASTR + c0];
            #pragma unroll
            for (int i = 0; i < 4; i++) {
                FMA4(acc[i], pv[i].x, vv[0]);
                FMA4(acc[i], pv[i].y, vv[1]);
                FMA4(acc[i], pv[i].z, vv[2]);
                FMA4(acc[i], pv[i].w, vv[3]);
            }
        }
    }

    #pragma unroll
    for (int i = 0; i < 4; i++) {
        const float invl = 1.0f / l[i];
        float4 o;
        o.x = acc[i][0] * invl; o.y = acc[i][1] * invl;
        o.z = acc[i][2] * invl; o.w = acc[i][3] * invl;
        *(float4*)&O[(rowBase + q0 + r0 + i) * D_MODEL + headOff + c0] = o;
    }
}

// ---------------------------------------------------------------------------
// Launch
// ---------------------------------------------------------------------------
#define ATTN_SMEM ((BQ + HDIM + BKT + BQ) * ASTR * (int)sizeof(float))

extern "C" void kernel_launch(void* const* d_in, const int* in_sizes, int n_in,
                              void* d_out, int out_size)
{
    const float* src = (const float*)d_in[0];
    const float* Wq  = (const float*)d_in[1];  const float* bq = (const float*)d_in[2];
    const float* Wk  = (const float*)d_in[3];  const float* bk = (const float*)d_in[4];
    const float* Wv  = (const float*)d_in[5];  const float* bv = (const float*)d_in[6];
    const float* Wo  = (const float*)d_in[7];  const float* bo = (const float*)d_in[8];
    const float* W1  = (const float*)d_in[9];  const float* b1 = (const float*)d_in[10];
    const float* W2  = (const float*)d_in[11]; const float* b2 = (const float*)d_in[12];
    const float* g1  = (const float*)d_in[13]; const float* be1 = (const float*)d_in[14];
    const float* g2  = (const float*)d_in[15]; const float* be2 = (const float*)d_in[16];
    float* out = (float*)d_out;

    float *ln, *q, *k, *v, *att, *x1, *h1;
    __nv_bfloat16 *ahi, *alo, *whi, *wlo;
    cudaGetSymbolAddress((void**)&ln,  g_ln);
    cudaGetSymbolAddress((void**)&q,   g_q);
    cudaGetSymbolAddress((void**)&k,   g_k);
    cudaGetSymbolAddress((void**)&v,   g_v);
    cudaGetSymbolAddress((void**)&att, g_att);
    cudaGetSymbolAddress((void**)&x1,  g_x1);
    cudaGetSymbolAddress((void**)&h1,  g_h1);
    cudaGetSymbolAddress((void**)&ahi, g_ahi);
    cudaGetSymbolAddress((void**)&alo, g_alo);
    cudaGetSymbolAddress((void**)&whi, g_whi);
    cudaGetSymbolAddress((void**)&wlo, g_wlo);

    cudaFuncSetAttribute(attn_kernel, cudaFuncAttributeMaxDynamicSharedMemorySize, ATTN_SMEM);
    cudaFuncSetAttribute(mm_gemm,     cudaFuncAttributeMaxDynamicSharedMemorySize, MMG_SMEM);

    const int nA4 = M_TOTAL * D_MODEL / 4;
    const int nW4 = D_MODEL * D_MODEL / 4;
    const dim3 gGemm(D_MODEL / 128, M_TOTAL / 128);  // (8, 64)
    const dim3 gAttn(SEQ / BQ, BATCH * NHEADS);

    // ln1 = LN(src); split activations once, reuse for Q/K/V
    ln_kernel<<<M_TOTAL, 256>>>(src, g1, be1, ln);
    split_kernel<<<nA4 / 256, 256>>>(ln, ahi, alo, nA4);

    split_kernel<<<nW4 / 256, 256>>>(Wq, whi, wlo, nW4);
    mm_gemm<<<gGemm, 256, MMG_SMEM>>>(ahi, alo, whi, wlo, bq, nullptr, q, 0);
    split_kernel<<<nW4 / 256, 256>>>(Wk, whi, wlo, nW4);
    mm_gemm<<<gGemm, 256, MMG_SMEM>>>(ahi, alo, whi, wlo, bk, nullptr, k, 0);
    split_kernel<<<nW4 / 256, 256>>>(Wv, whi, wlo, nW4);
    mm_gemm<<<gGemm, 256, MMG_SMEM>>>(ahi, alo, whi, wlo, bv, nullptr, v, 0);

    attn_kernel<<<gAttn, 256, ATTN_SMEM>>>(q, k, v, att);

    // x1 = src + att @ Wo^T + bo
    split_kernel<<<nA4 / 256, 256>>>(att, ahi, alo, nA4);
    split_kernel<<<nW4 / 256, 256>>>(Wo, whi, wlo, nW4);
    mm_gemm<<<gGemm, 256, MMG_SMEM>>>(ahi, alo, whi, wlo, bo, src, x1, 0);

    // ln2; h1 = relu(ln2 @ W1^T + b1)
    ln_kernel<<<M_TOTAL, 256>>>(x1, g2, be2, ln);
    split_kernel<<<nA4 / 256, 256>>>(ln, ahi, alo, nA4);
    split_kernel<<<nW4 / 256, 256>>>(W1, whi, wlo, nW4);
    mm_gemm<<<gGemm, 256, MMG_SMEM>>>(ahi, alo, whi, wlo, b1, nullptr, h1, 1);

    // out = x1 + h1 @ W2^T + b2
    split_kernel<<<nA4 / 256, 256>>>(h1, ahi, alo, nA4);
    split_kernel<<<nW4 / 256, 256>>>(W2, whi, wlo, nW4);
    mm_gemm<<<gGemm, 256, MMG_SMEM>>>(ahi, alo, whi, wlo, b2, x1, out, 0);
}

// round 4
// speedup vs baseline: 3.4311x; 2.0119x over previous
#include <cuda_runtime.h>
#include <cuda_bf16.h>
#include <math.h>
#include <stdint.h>

#define D_MODEL 1024
#define SEQ     2048
#define BATCH   4
#define NHEADS  16
#define HDIM    64
#define M_TOTAL (BATCH * SEQ)      // 8192
#define LN_EPS  1e-5f

// ---------------------------------------------------------------------------
// Scratch buffers (allocation-free rule: __device__ globals)
// ---------------------------------------------------------------------------
__device__ float g_x1 [M_TOTAL * D_MODEL];
__device__ __nv_bfloat16 g_ahi[M_TOTAL * D_MODEL];
__device__ __nv_bfloat16 g_alo[M_TOTAL * D_MODEL];
__device__ __nv_bfloat16 g_qhi[M_TOTAL * D_MODEL];
__device__ __nv_bfloat16 g_qlo[M_TOTAL * D_MODEL];
__device__ __nv_bfloat16 g_khi[M_TOTAL * D_MODEL];
__device__ __nv_bfloat16 g_klo[M_TOTAL * D_MODEL];
__device__ __nv_bfloat16 g_vhi[M_TOTAL * D_MODEL];
__device__ __nv_bfloat16 g_vlo[M_TOTAL * D_MODEL];
__device__ __nv_bfloat16 g_whi[D_MODEL * D_MODEL];
__device__ __nv_bfloat16 g_wlo[D_MODEL * D_MODEL];

// ---------------------------------------------------------------------------
// Portable tensor-core helpers (sm_80+ ISA: mma.sync / ldmatrix / cp.async)
// ---------------------------------------------------------------------------
__device__ __forceinline__ uint32_t smem_u32(const void* p) {
    uint32_t a;
    asm("{ .reg .u64 t; cvta.to.shared.u64 t, %1; cvt.u32.u64 %0, t; }" : "=r"(a) : "l"(p));
    return a;
}
#define CP_ASYNC16(sa, g) \
    asm volatile("cp.async.cg.shared.global [%0], [%1], 16;" :: "r"(sa), "l"(g) : "memory")
#define CP_COMMIT() asm volatile("cp.async.commit_group;" ::: "memory")
#define CP_WAIT0()  asm volatile("cp.async.wait_group 0;" ::: "memory")
#define CP_WAIT1()  asm volatile("cp.async.wait_group 1;" ::: "memory")

__device__ __forceinline__ void ldsm4(uint32_t* r, uint32_t addr) {
    asm volatile("ldmatrix.sync.aligned.m8n8.x4.shared.b16 {%0,%1,%2,%3}, [%4];"
                 : "=r"(r[0]), "=r"(r[1]), "=r"(r[2]), "=r"(r[3]) : "r"(addr));
}
__device__ __forceinline__ void ldsm4t(uint32_t* r, uint32_t addr) {
    asm volatile("ldmatrix.sync.aligned.m8n8.x4.trans.shared.b16 {%0,%1,%2,%3}, [%4];"
                 : "=r"(r[0]), "=r"(r[1]), "=r"(r[2]), "=r"(r[3]) : "r"(addr));
}
__device__ __forceinline__ void mma_bf16(float* d, const uint32_t* a, const uint32_t* b) {
    asm volatile("mma.sync.aligned.m16n8k16.row.col.f32.bf16.bf16.f32 "
                 "{%0,%1,%2,%3}, {%4,%5,%6,%7}, {%8,%9}, {%0,%1,%2,%3};"
                 : "+f"(d[0]), "+f"(d[1]), "+f"(d[2]), "+f"(d[3])
                 : "r"(a[0]), "r"(a[1]), "r"(a[2]), "r"(a[3]), "r"(b[0]), "r"(b[1]));
}
// pack two f32 -> bf16x2 reg: low half = lo, high half = hi
#define PACK_BF16X2(d, lo, hi) \
    asm("cvt.rn.bf16x2.f32 %0, %2, %1;" : "=r"(d) : "f"(lo), "f"(hi))
#define EX2(d, x) asm("ex2.approx.ftz.f32 %0, %1;" : "=f"(d) : "f"(x))

__device__ __forceinline__ void split2(float v0, float v1, uint32_t& hi, uint32_t& lo) {
    PACK_BF16X2(hi, v0, v1);
    const float h0 = __uint_as_float(hi << 16);
    const float h1 = __uint_as_float(hi & 0xffff0000u);
    PACK_BF16X2(lo, v0 - h0, v1 - h1);
}

// ---------------------------------------------------------------------------
// fp32 -> bf16 hi/lo split (weights)
// ---------------------------------------------------------------------------
__global__ void __launch_bounds__(256) split_kernel(
    const float* __restrict__ x, __nv_bfloat16* __restrict__ hi,
    __nv_bfloat16* __restrict__ lo, int n4)
{
    const int i = blockIdx.x * 256 + threadIdx.x;
    if (i >= n4) return;
    const float4 v = ((const float4*)x)[i];
    uint32_t h0, l0, h1, l1;
    split2(v.x, v.y, h0, l0);
    split2(v.z, v.w, h1, l1);
    ((uint32_t*)hi)[2 * i] = h0; ((uint32_t*)hi)[2 * i + 1] = h1;
    ((uint32_t*)lo)[2 * i] = l0; ((uint32_t*)lo)[2 * i + 1] = l1;
}

// ---------------------------------------------------------------------------
// Fused LayerNorm + bf16 hi/lo split: one block per row
// ---------------------------------------------------------------------------
__global__ void __launch_bounds__(256) ln_split_kernel(
    const float* __restrict__ x, const float* __restrict__ g,
    const float* __restrict__ b, __nv_bfloat16* __restrict__ hi,
    __nv_bfloat16* __restrict__ lo)
{
    __shared__ float red[16];
    const int row = blockIdx.x;
    const int tid = threadIdx.x;
    const float4 v = ((const float4*)(x + (size_t)row * D_MODEL))[tid];

    float s  = v.x + v.y + v.z + v.w;
    float ss = v.x * v.x + v.y * v.y + v.z * v.z + v.w * v.w;
    #pragma unroll
    for (int o = 16; o; o >>= 1) {
        s  += __shfl_xor_sync(0xffffffffu, s,  o);
        ss += __shfl_xor_sync(0xffffffffu, ss, o);
    }
    const int wid = tid >> 5;
    if ((tid & 31) == 0) { red[wid] = s; red[8 + wid] = ss; }
    __syncthreads();
    float S = 0.f, SS = 0.f;
    #pragma unroll
    for (int w = 0; w < 8; w++) { S += red[w]; SS += red[8 + w]; }
    const float mu   = S * (1.0f / D_MODEL);
    const float var  = SS * (1.0f / D_MODEL) - mu * mu;
    const float rstd = rsqrtf(var + LN_EPS);

    const float4 gv = ((const float4*)g)[tid];
    const float4 bv = ((const float4*)b)[tid];
    const float o0 = (v.x - mu) * rstd * gv.x + bv.x;
    const float o1 = (v.y - mu) * rstd * gv.y + bv.y;
    const float o2 = (v.z - mu) * rstd * gv.z + bv.z;
    const float o3 = (v.w - mu) * rstd * gv.w + bv.w;
    uint32_t h0, l0, h1, l1;
    split2(o0, o1, h0, l0);
    split2(o2, o3, h1, l1);
    const size_t base = (size_t)row * (D_MODEL / 2) + tid * 2;
    ((uint32_t*)hi)[base] = h0; ((uint32_t*)hi)[base + 1] = h1;
    ((uint32_t*)lo)[base] = l0; ((uint32_t*)lo)[base + 1] = l1;
}

// ---------------------------------------------------------------------------
// mma.sync GEMM: C = A * W^T + bias [+ReLU] [+res]; out fp32 or bf16 hi/lo
// ---------------------------------------------------------------------------
#define TILE_B   16384
#define STAGE_B  (4 * TILE_B)
#define MMG_SMEM (2 * STAGE_B)

__device__ __forceinline__ uint32_t swadr(uint32_t tbase, int row, int chunk) {
    return tbase + row * 128 + (((chunk ^ row) & 7) << 4) + ((chunk & ~7) << 4);
}

__global__ void __launch_bounds__(256, 1)
mm_gemm(const __nv_bfloat16* __restrict__ Ahi, const __nv_bfloat16* __restrict__ Alo,
        const __nv_bfloat16* __restrict__ Whi, const __nv_bfloat16* __restrict__ Wlo,
        const float* __restrict__ bias, const float* __restrict__ res,
        float* __restrict__ Cf, __nv_bfloat16* __restrict__ Chi,
        __nv_bfloat16* __restrict__ Clo, int doRelu)
{
    extern __shared__ char smem[];
    const uint32_t sb = smem_u32(smem);
    const int tid = threadIdx.x;
    const int wid = tid >> 5;
    const int lid = tid & 31;
    const int warpM = wid >> 2;
    const int warpN = wid & 3;
    const int bn = blockIdx.x * 128;
    const int bm = blockIdx.y * 128;

    const __nv_bfloat16* baseA0 = Ahi + (size_t)bm * 1024;
    const __nv_bfloat16* baseA1 = Alo + (size_t)bm * 1024;
    const __nv_bfloat16* baseW0 = Whi + (size_t)bn * 1024;
    const __nv_bfloat16* baseW1 = Wlo + (size_t)bn * 1024;

    #define LOAD_CHUNK(stg, k0) do {                                              \
        const uint32_t _sbase = sb + (stg) * STAGE_B;                             \
        _Pragma("unroll")                                                         \
        for (int i = 0; i < 16; i++) {                                            \
            const int tile = i >> 2;                                              \
            const int idx  = (tid + i * 256) & 1023;                              \
            const int r    = idx >> 3;                                            \
            const int c8   = idx & 7;                                             \
            const __nv_bfloat16* gp =                                             \
                (tile == 0 ? baseA0 : tile == 1 ? baseA1 :                        \
                 tile == 2 ? baseW0 : baseW1) + (size_t)r * 1024 + (k0) + c8 * 8; \
            const uint32_t sa = _sbase + tile * TILE_B +                          \
                (uint32_t)(r * 128 + (((c8 ^ r) & 7) << 4));                      \
            CP_ASYNC16(sa, gp);                                                   \
        }                                                                         \
        CP_COMMIT();                                                              \
    } while (0)

    float acc[4][4][4];
    #pragma unroll
    for (int a = 0; a < 4; a++)
        #pragma unroll
        for (int b = 0; b < 4; b++)
            #pragma unroll
            for (int c = 0; c < 4; c++) acc[a][b][c] = 0.f;

    const int aRow = warpM * 64 + (lid & 15);
    const int aChk = lid >> 4;
    const int bRow = warpN * 32 + ((lid >= 16) ? 8 : 0) + (lid & 7);
    const int bChk = (lid >> 3) & 1;

    LOAD_CHUNK(0, 0);

    #pragma unroll 1
    for (int c = 0; c < 16; c++) {
        const int s = c & 1;
        __syncthreads();
        if (c < 15) { LOAD_CHUNK(s ^ 1, (c + 1) * 64); CP_WAIT1(); }
        else        { CP_WAIT0(); }
        __syncthreads();

        const uint32_t sA0 = sb + s * STAGE_B;
        const uint32_t sA1 = sA0 + TILE_B;
        const uint32_t sW0 = sA0 + 2 * TILE_B;
        const uint32_t sW1 = sA0 + 3 * TILE_B;

        #pragma unroll
        for (int s16 = 0; s16 < 4; s16++) {
            const int kc = s16 * 2;
            uint32_t Bh[4][2], Bl[4][2];
            #pragma unroll
            for (int pair = 0; pair < 2; pair++) {
                const int r = bRow + pair * 16;
                ldsm4(&Bh[pair * 2][0], swadr(sW0, r, kc + bChk));
                ldsm4(&Bl[pair * 2][0], swadr(sW1, r, kc + bChk));
            }
            #pragma unroll
            for (int mt = 0; mt < 4; mt++) {
                uint32_t Ah[4], Al[4];
                const int r = aRow + mt * 16;
                ldsm4(Ah, swadr(sA0, r, kc + aChk));
                ldsm4(Al, swadr(sA1, r, kc + aChk));
                #pragma unroll
                for (int nt = 0; nt < 4; nt++) {
                    mma_bf16(acc[mt][nt], Ah, Bh[nt]);
                    mma_bf16(acc[mt][nt], Ah, Bl[nt]);
                    mma_bf16(acc[mt][nt], Al, Bh[nt]);
                }
            }
        }
    }

    const int rowoff = lid >> 2;
    const int coloff = (lid & 3) * 2;
    #pragma unroll
    for (int mt = 0; mt < 4; mt++) {
        #pragma unroll
        for (int nt = 0; nt < 4; nt++) {
            const int gn = bn + warpN * 32 + nt * 8 + coloff;
            const float b0 = __ldg(&bias[gn]);
            const float b1 = __ldg(&bias[gn + 1]);
            #pragma unroll
            for (int half = 0; half < 2; half++) {
                const int gm = bm + warpM * 64 + mt * 16 + rowoff + half * 8;
                float v0 = acc[mt][nt][half * 2 + 0] + b0;
                float v1 = acc[mt][nt][half * 2 + 1] + b1;
                if (doRelu) { v0 = fmaxf(v0, 0.f); v1 = fmaxf(v1, 0.f); }
                const size_t off = (size_t)gm * 1024 + gn;
                if (res) {
                    const float2 rv = *(const float2*)&res[off];
                    v0 += rv.x; v1 += rv.y;
                }
                if (Cf) {
                    *(float2*)&Cf[off] = make_float2(v0, v1);
                } else {
                    uint32_t h, l;
                    split2(v0, v1, h, l);
                    *(uint32_t*)&Chi[off] = h;
                    *(uint32_t*)&Clo[off] = l;
                }
            }
        }
    }
}

// ---------------------------------------------------------------------------
// Flash attention on mma.sync, bf16x3 everywhere.
// Per CTA: one (b,h), 128 queries, 8 warps x 16 rows. K/V tiles of 64 keys,
// double-buffered cp.async. Online softmax in D-fragments.
// smem: Qhi(16K) Qlo(16K) | stage0: Khi Klo Vhi Vlo (8K each) | stage1: same
// ---------------------------------------------------------------------------
#define AQ 128
#define AK 64
#define ATT_Q    0
#define ATT_ST   32768
#define ATT_STB  32768
#define ATT_SMEM (ATT_ST + 2 * ATT_STB)   // 98304

__global__ void __launch_bounds__(256, 1) attn_mma(
    const __nv_bfloat16* __restrict__ Qhi, const __nv_bfloat16* __restrict__ Qlo,
    const __nv_bfloat16* __restrict__ Khi, const __nv_bfloat16* __restrict__ Klo,
    const __nv_bfloat16* __restrict__ Vhi, const __nv_bfloat16* __restrict__ Vlo,
    __nv_bfloat16* __restrict__ Ohi, __nv_bfloat16* __restrict__ Olo)
{
    extern __shared__ char smem[];
    const uint32_t sb = smem_u32(smem);
    const int tid = threadIdx.x;
    const int wid = tid >> 5;
    const int lid = tid & 31;
    const int bh  = blockIdx.y;
    const int b   = bh >> 4;
    const int h   = bh & 15;
    const int q0  = blockIdx.x * AQ;
    const size_t rowBase = (size_t)b * SEQ;
    const int hcol = h * HDIM;

    // ---- Q load: 2 tiles x 128 rows x 8 chunks = 2048 chunks, 8/thread ----
    {
        #pragma unroll
        for (int i = 0; i < 8; i++) {
            const int tile = i >> 2;                      // 0: hi, 1: lo
            const int idx  = (tid + i * 256) & 1023;
            const int r    = idx >> 3;
            const int c8   = idx & 7;
            const __nv_bfloat16* gp = (tile ? Qlo : Qhi)
                + (rowBase + q0 + r) * 1024 + hcol + c8 * 8;
            const uint32_t sa = sb + ATT_Q + tile * 16384
                + (uint32_t)(r * 128 + (((c8 ^ r) & 7) << 4));
            CP_ASYNC16(sa, gp);
        }
        CP_COMMIT();
    }

    // ---- K/V stage load: 4 tiles x 64 rows x 8 chunks, 8/thread ----
    #define LOAD_KV(stg, kt) do {                                               \
        const uint32_t _sbase = sb + ATT_ST + (stg) * ATT_STB;                  \
        _Pragma("unroll")                                                       \
        for (int i = 0; i < 8; i++) {                                           \
            const int tile = i >> 1;                                            \
            const int idx  = (tid + (i & 1) * 256) & 511;                       \
            const int r    = idx >> 3;                                          \
            const int c8   = idx & 7;                                           \
            const __nv_bfloat16* gp =                                           \
                (tile == 0 ? Khi : tile == 1 ? Klo : tile == 2 ? Vhi : Vlo)     \
                + (rowBase + (kt) * AK + r) * 1024 + hcol + c8 * 8;             \
            const uint32_t sa = _sbase + tile * 8192 +                          \
                (uint32_t)(r * 128 + (((c8 ^ r) & 7) << 4));                    \
            CP_ASYNC16(sa, gp);                                                 \
        }                                                                       \
        CP_COMMIT();                                                            \
    } while (0)

    LOAD_KV(0, 0);
    CP_WAIT0();
    __syncthreads();

    // ---- persistent Q fragments ----
    uint32_t Qh[4][4], Ql[4][4];
    {
        const int r = wid * 16 + (lid & 15);
        const int ck = lid >> 4;
        #pragma unroll
        for (int t = 0; t < 4; t++) {
            ldsm4(Qh[t], swadr(sb + ATT_Q,         r, 2 * t + ck));
            ldsm4(Ql[t], swadr(sb + ATT_Q + 16384, r, 2 * t + ck));
        }
    }

    // ---- state ----
    float o[8][4];
    #pragma unroll
    for (int j = 0; j < 8; j++)
        #pragma unroll
        for (int e = 0; e < 4; e++) o[j][e] = 0.f;
    float m0 = -INFINITY, m1 = -INFINITY, l0 = 0.f, l1 = 0.f;
    const float cs = 0.125f * 1.4426950408889634f;   // scale * log2(e)

    // lane components for K (non-trans) and V (trans) ldmatrix
    const int kRowL = ((lid >= 16) ? 8 : 0) + (lid & 7);
    const int kChkL = (lid >> 3) & 1;
    const int vT    = lid >> 3;
    const int vKeyL = ((vT & 1) << 3) + (lid & 7);
    const int vChkL = vT >> 1;

    #pragma unroll 1
    for (int kt = 0; kt < SEQ / AK; kt++) {
        const int s = kt & 1;
        __syncthreads();
        if (kt < SEQ / AK - 1) { LOAD_KV(s ^ 1, kt + 1); CP_WAIT1(); }
        else                   { CP_WAIT0(); }
        __syncthreads();

        const uint32_t sKh = sb + ATT_ST + s * ATT_STB;
        const uint32_t sKl = sKh + 8192;
        const uint32_t sVh = sKh + 16384;
        const uint32_t sVl = sKh + 24576;

        // ---- S = Q K^T (bf16x3) ----
        float sc[8][4];
        #pragma unroll
        for (int j = 0; j < 8; j++)
            #pragma unroll
            for (int e = 0; e < 4; e++) sc[j][e] = 0.f;

        #pragma unroll
        for (int t = 0; t < 4; t++) {
            #pragma unroll
            for (int kp = 0; kp < 4; kp++) {
                uint32_t kh[4], kl[4];
                const int r = kp * 16 + kRowL;
                ldsm4(kh, swadr(sKh, r, 2 * t + kChkL));
                ldsm4(kl, swadr(sKl, r, 2 * t + kChkL));
                mma_bf16(sc[2 * kp],     Qh[t], kh);
                mma_bf16(sc[2 * kp + 1], Qh[t], kh + 2);
                mma_bf16(sc[2 * kp],     Qh[t], kl);
                mma_bf16(sc[2 * kp + 1], Qh[t], kl + 2);
                mma_bf16(sc[2 * kp],     Ql[t], kh);
                mma_bf16(sc[2 * kp + 1], Ql[t], kh + 2);
            }
        }

        // ---- online softmax (rows: r0 = lid>>2, r1 = r0+8) ----
        float mx0 = -INFINITY, mx1 = -INFINITY;
        #pragma unroll
        for (int j = 0; j < 8; j++) {
            mx0 = fmaxf(mx0, fmaxf(sc[j][0], sc[j][1]));
            mx1 = fmaxf(mx1, fmaxf(sc[j][2], sc[j][3]));
        }
        mx0 *= cs; mx1 *= cs;
        #pragma unroll
        for (int d = 1; d < 4; d <<= 1) {
            mx0 = fmaxf(mx0, __shfl_xor_sync(0xffffffffu, mx0, d));
            mx1 = fmaxf(mx1, __shfl_xor_sync(0xffffffffu, mx1, d));
        }
        const float m0n = fmaxf(m0, mx0);
        const float m1n = fmaxf(m1, mx1);
        float sc0, sc1;
        EX2(sc0, m0 - m0n);
        EX2(sc1, m1 - m1n);
        m0 = m0n; m1 = m1n;

        float rs0 = 0.f, rs1 = 0.f;
        uint32_t ph01[8], ph23[8], pl01[8], pl23[8];
        #pragma unroll
        for (int j = 0; j < 8; j++) {
            float p00, p01, p10, p11;
            EX2(p00, fmaf(sc[j][0], cs, -m0));
            EX2(p01, fmaf(sc[j][1], cs, -m0));
            EX2(p10, fmaf(sc[j][2], cs, -m1));
            EX2(p11, fmaf(sc[j][3], cs, -m1));
            rs0 += p00 + p01;
            rs1 += p10 + p11;
            split2(p00, p01, ph01[j], pl01[j]);
            split2(p10, p11, ph23[j], pl23[j]);
        }
        #pragma unroll
        for (int d = 1; d < 4; d <<= 1) {
            rs0 += __shfl_xor_sync(0xffffffffu, rs0, d);
            rs1 += __shfl_xor_sync(0xffffffffu, rs1, d);
        }
        l0 = l0 * sc0 + rs0;
        l1 = l1 * sc1 + rs1;
        #pragma unroll
        for (int j = 0; j < 8; j++) {
            o[j][0] *= sc0; o[j][1] *= sc0;
            o[j][2] *= sc1; o[j][3] *= sc1;
        }

        // ---- O += P V (bf16x3) ----
        #pragma unroll
        for (int kb = 0; kb < 4; kb++) {
            const uint32_t pa_h[4] = { ph01[2 * kb], ph23[2 * kb],
                                       ph01[2 * kb + 1], ph23[2 * kb + 1] };
            const uint32_t pa_l[4] = { pl01[2 * kb], pl23[2 * kb],
                                       pl01[2 * kb + 1], pl23[2 * kb + 1] };
            #pragma unroll
            for (int np = 0; np < 4; np++) {
                uint32_t vh[4], vl[4];
                const int key = kb * 16 + vKeyL;
                const int ck  = np * 2 + vChkL;
                ldsm4t(vh, swadr(sVh, key, ck));
                ldsm4t(vl, swadr(sVl, key, ck));
                mma_bf16(o[2 * np],     pa_h, vh);
                mma_bf16(o[2 * np + 1], pa_h, vh + 2);
                mma_bf16(o[2 * np],     pa_h, vl);
                mma_bf16(o[2 * np + 1], pa_h, vl + 2);
                mma_bf16(o[2 * np],     pa_l, vh);
                mma_bf16(o[2 * np + 1], pa_l, vh + 2);
            }
        }
    }

    // ---- epilogue: divide by l, write bf16 hi/lo ----
    const float il0 = 1.0f / l0;
    const float il1 = 1.0f / l1;
    const size_t row0 = rowBase + q0 + wid * 16 + (lid >> 2);
    const size_t row1 = row0 + 8;
    const int cb = hcol + (lid & 3) * 2;
    #pragma unroll
    for (int j = 0; j < 8; j++) {
        const int col = cb + j * 8;
        uint32_t h, l;
        split2(o[j][0] * il0, o[j][1] * il0, h, l);
        *(uint32_t*)&Ohi[row0 * 1024 + col] = h;
        *(uint32_t*)&Olo[row0 * 1024 + col] = l;
        split2(o[j][2] * il1, o[j][3] * il1, h, l);
        *(uint32_t*)&Ohi[row1 * 1024 + col] = h;
        *(uint32_t*)&Olo[row1 * 1024 + col] = l;
    }
}

// ---------------------------------------------------------------------------
// Launch
// ---------------------------------------------------------------------------
extern "C" void kernel_launch(void* const* d_in, const int* in_sizes, int n_in,
                              void* d_out, int out_size)
{
    const float* src = (const float*)d_in[0];
    const float* Wq  = (const float*)d_in[1];  const float* bq = (const float*)d_in[2];
    const float* Wk  = (const float*)d_in[3];  const float* bk = (const float*)d_in[4];
    const float* Wv  = (const float*)d_in[5];  const float* bv = (const float*)d_in[6];
    const float* Wo  = (const float*)d_in[7];  const float* bo = (const float*)d_in[8];
    const float* W1  = (const float*)d_in[9];  const float* b1 = (const float*)d_in[10];
    const float* W2  = (const float*)d_in[11]; const float* b2 = (const float*)d_in[12];
    const float* g1  = (const float*)d_in[13]; const float* be1 = (const float*)d_in[14];
    const float* g2  = (const float*)d_in[15]; const float* be2 = (const float*)d_in[16];
    float* out = (float*)d_out;

    float* x1;
    __nv_bfloat16 *ahi, *alo, *whi, *wlo, *qhi, *qlo, *khi, *klo, *vhi, *vlo;
    cudaGetSymbolAddress((void**)&x1,  g_x1);
    cudaGetSymbolAddress((void**)&ahi, g_ahi);
    cudaGetSymbolAddress((void**)&alo, g_alo);
    cudaGetSymbolAddress((void**)&whi, g_whi);
    cudaGetSymbolAddress((void**)&wlo, g_wlo);
    cudaGetSymbolAddress((void**)&qhi, g_qhi);
    cudaGetSymbolAddress((void**)&qlo, g_qlo);
    cudaGetSymbolAddress((void**)&khi, g_khi);
    cudaGetSymbolAddress((void**)&klo, g_klo);
    cudaGetSymbolAddress((void**)&vhi, g_vhi);
    cudaGetSymbolAddress((void**)&vlo, g_vlo);

    cudaFuncSetAttribute(mm_gemm,  cudaFuncAttributeMaxDynamicSharedMemorySize, MMG_SMEM);
    cudaFuncSetAttribute(attn_mma, cudaFuncAttributeMaxDynamicSharedMemorySize, ATT_SMEM);

    const int nW4 = D_MODEL * D_MODEL / 4;
    const dim3 gGemm(D_MODEL / 128, M_TOTAL / 128);  // (8, 64)
    const dim3 gAttn(SEQ / AQ, BATCH * NHEADS);      // (16, 64)

    // ln1(src) -> bf16 split
    ln_split_kernel<<<M_TOTAL, 256>>>(src, g1, be1, ahi, alo);

    // Q/K/V projections (bf16 hi/lo out)
    split_kernel<<<nW4 / 256, 256>>>(Wq, whi, wlo, nW4);
    mm_gemm<<<gGemm, 256, MMG_SMEM>>>(ahi, alo, whi, wlo, bq, nullptr, nullptr, qhi, qlo, 0);
    split_kernel<<<nW4 / 256, 256>>>(Wk, whi, wlo, nW4);
    mm_gemm<<<gGemm, 256, MMG_SMEM>>>(ahi, alo, whi, wlo, bk, nullptr, nullptr, khi, klo, 0);
    split_kernel<<<nW4 / 256, 256>>>(Wv, whi, wlo, nW4);
    mm_gemm<<<gGemm, 256, MMG_SMEM>>>(ahi, alo, whi, wlo, bv, nullptr, nullptr, vhi, vlo, 0);

    // attention -> bf16 hi/lo (directly consumable by Wo gemm)
    attn_mma<<<gAttn, 256, ATT_SMEM>>>(qhi, qlo, khi, klo, vhi, vlo, ahi, alo);

    // x1 = src + att @ Wo^T + bo   (fp32 out)
    split_kernel<<<nW4 / 256, 256>>>(Wo, whi, wlo, nW4);
    mm_gemm<<<gGemm, 256, MMG_SMEM>>>(ahi, alo, whi, wlo, bo, src, x1, nullptr, nullptr, 0);

    // ln2(x1) -> bf16 split; h1 = relu(... @ W1^T + b1) (bf16 out, reuse q bufs)
    ln_split_kernel<<<M_TOTAL, 256>>>(x1, g2, be2, ahi, alo);
    split_kernel<<<nW4 / 256, 256>>>(W1, whi, wlo, nW4);
    mm_gemm<<<gGemm, 256, MMG_SMEM>>>(ahi, alo, whi, wlo, b1, nullptr, nullptr, qhi, qlo, 1);

    // out = x1 + h1 @ W2^T + b2
    split_kernel<<<nW4 / 256, 256>>>(W2, whi, wlo, nW4);
    mm_gemm<<<gGemm, 256, MMG_SMEM>>>(qhi, qlo, whi, wlo, b2, x1, out, nullptr, nullptr, 0);
}

// round 5
// speedup vs baseline: 3.5503x; 1.0347x over previous
#include <cuda_runtime.h>
#include <cuda_bf16.h>
#include <math.h>
#include <stdint.h>

#define D_MODEL 1024
#define SEQ     2048
#define BATCH   4
#define NHEADS  16
#define HDIM    64
#define M_TOTAL (BATCH * SEQ)      // 8192
#define LN_EPS  1e-5f

// ---------------------------------------------------------------------------
// Scratch buffers (allocation-free rule: __device__ globals)
// ---------------------------------------------------------------------------
__device__ float g_x1 [M_TOTAL * D_MODEL];
__device__ __nv_bfloat16 g_ahi[M_TOTAL * D_MODEL];
__device__ __nv_bfloat16 g_alo[M_TOTAL * D_MODEL];
__device__ __nv_bfloat16 g_qhi[M_TOTAL * D_MODEL];
__device__ __nv_bfloat16 g_qlo[M_TOTAL * D_MODEL];
__device__ __nv_bfloat16 g_khi[M_TOTAL * D_MODEL];
__device__ __nv_bfloat16 g_klo[M_TOTAL * D_MODEL];
__device__ __nv_bfloat16 g_vhi[M_TOTAL * D_MODEL];
__device__ __nv_bfloat16 g_vlo[M_TOTAL * D_MODEL];
__device__ __nv_bfloat16 g_whi[6 * D_MODEL * D_MODEL];
__device__ __nv_bfloat16 g_wlo[6 * D_MODEL * D_MODEL];

// ---------------------------------------------------------------------------
// Portable tensor-core helpers (sm_80+ ISA: mma.sync / ldmatrix / cp.async)
// ---------------------------------------------------------------------------
__device__ __forceinline__ uint32_t smem_u32(const void* p) {
    uint32_t a;
    asm("{ .reg .u64 t; cvta.to.shared.u64 t, %1; cvt.u32.u64 %0, t; }" : "=r"(a) : "l"(p));
    return a;
}
#define CP_ASYNC16(sa, g) \
    asm volatile("cp.async.cg.shared.global [%0], [%1], 16;" :: "r"(sa), "l"(g) : "memory")
#define CP_COMMIT() asm volatile("cp.async.commit_group;" ::: "memory")
#define CP_WAIT0()  asm volatile("cp.async.wait_group 0;" ::: "memory")
#define CP_WAIT1()  asm volatile("cp.async.wait_group 1;" ::: "memory")

__device__ __forceinline__ void ldsm4(uint32_t* r, uint32_t addr) {
    asm volatile("ldmatrix.sync.aligned.m8n8.x4.shared.b16 {%0,%1,%2,%3}, [%4];"
                 : "=r"(r[0]), "=r"(r[1]), "=r"(r[2]), "=r"(r[3]) : "r"(addr));
}
__device__ __forceinline__ void ldsm4t(uint32_t* r, uint32_t addr) {
    asm volatile("ldmatrix.sync.aligned.m8n8.x4.trans.shared.b16 {%0,%1,%2,%3}, [%4];"
                 : "=r"(r[0]), "=r"(r[1]), "=r"(r[2]), "=r"(r[3]) : "r"(addr));
}
__device__ __forceinline__ void mma_bf16(float* d, const uint32_t* a, const uint32_t* b) {
    asm volatile("mma.sync.aligned.m16n8k16.row.col.f32.bf16.bf16.f32 "
                 "{%0,%1,%2,%3}, {%4,%5,%6,%7}, {%8,%9}, {%0,%1,%2,%3};"
                 : "+f"(d[0]), "+f"(d[1]), "+f"(d[2]), "+f"(d[3])
                 : "r"(a[0]), "r"(a[1]), "r"(a[2]), "r"(a[3]), "r"(b[0]), "r"(b[1]));
}
// pack two f32 -> bf16x2 reg: low half = first arg, high half = second arg
#define PACK_BF16X2(d, lo, hi) \
    asm("cvt.rn.bf16x2.f32 %0, %2, %1;" : "=r"(d) : "f"(lo), "f"(hi))
#define EX2(d, x) asm("ex2.approx.ftz.f32 %0, %1;" : "=f"(d) : "f"(x))

__device__ __forceinline__ void split2(float v0, float v1, uint32_t& hi, uint32_t& lo) {
    PACK_BF16X2(hi, v0, v1);
    const float h0 = __uint_as_float(hi << 16);
    const float h1 = __uint_as_float(hi & 0xffff0000u);
    PACK_BF16X2(lo, v0 - h0, v1 - h1);
}

// ---------------------------------------------------------------------------
// All six weight splits in one launch: grid.y selects weight
// ---------------------------------------------------------------------------
__global__ void __launch_bounds__(256) wsplit6_kernel(
    const float* __restrict__ w0, const float* __restrict__ w1,
    const float* __restrict__ w2, const float* __restrict__ w3,
    const float* __restrict__ w4, const float* __restrict__ w5,
    __nv_bfloat16* __restrict__ hi, __nv_bfloat16* __restrict__ lo)
{
    const int ws = blockIdx.y;
    const float* src = (ws == 0) ? w0 : (ws == 1) ? w1 : (ws == 2) ? w2
                     : (ws == 3) ? w3 : (ws == 4) ? w4 : w5;
    const int i = blockIdx.x * 256 + threadIdx.x;          // 0..262143
    const float4 v = ((const float4*)src)[i];
    uint32_t h0, l0, h1, l1;
    split2(v.x, v.y, h0, l0);
    split2(v.z, v.w, h1, l1);
    const size_t base = (size_t)ws * (D_MODEL * D_MODEL / 2) + 2 * i;
    ((uint32_t*)hi)[base] = h0; ((uint32_t*)hi)[base + 1] = h1;
    ((uint32_t*)lo)[base] = l0; ((uint32_t*)lo)[base + 1] = l1;
}

// ---------------------------------------------------------------------------
// Fused LayerNorm + bf16 hi/lo split: one block per row
// ---------------------------------------------------------------------------
__global__ void __launch_bounds__(256) ln_split_kernel(
    const float* __restrict__ x, const float* __restrict__ g,
    const float* __restrict__ b, __nv_bfloat16* __restrict__ hi,
    __nv_bfloat16* __restrict__ lo)
{
    __shared__ float red[16];
    const int row = blockIdx.x;
    const int tid = threadIdx.x;
    const float4 v = ((const float4*)(x + (size_t)row * D_MODEL))[tid];

    float s  = v.x + v.y + v.z + v.w;
    float ss = v.x * v.x + v.y * v.y + v.z * v.z + v.w * v.w;
    #pragma unroll
    for (int o = 16; o; o >>= 1) {
        s  += __shfl_xor_sync(0xffffffffu, s,  o);
        ss += __shfl_xor_sync(0xffffffffu, ss, o);
    }
    const int wid = tid >> 5;
    if ((tid & 31) == 0) { red[wid] = s; red[8 + wid] = ss; }
    __syncthreads();
    float S = 0.f, SS = 0.f;
    #pragma unroll
    for (int w = 0; w < 8; w++) { S += red[w]; SS += red[8 + w]; }
    const float mu   = S * (1.0f / D_MODEL);
    const float var  = SS * (1.0f / D_MODEL) - mu * mu;
    const float rstd = rsqrtf(var + LN_EPS);

    const float4 gv = ((const float4*)g)[tid];
    const float4 bv = ((const float4*)b)[tid];
    const float o0 = (v.x - mu) * rstd * gv.x + bv.x;
    const float o1 = (v.y - mu) * rstd * gv.y + bv.y;
    const float o2 = (v.z - mu) * rstd * gv.z + bv.z;
    const float o3 = (v.w - mu) * rstd * gv.w + bv.w;
    uint32_t h0, l0, h1, l1;
    split2(o0, o1, h0, l0);
    split2(o2, o3, h1, l1);
    const size_t base = (size_t)row * (D_MODEL / 2) + tid * 2;
    ((uint32_t*)hi)[base] = h0; ((uint32_t*)hi)[base + 1] = h1;
    ((uint32_t*)lo)[base] = l0; ((uint32_t*)lo)[base + 1] = l1;
}

// ---------------------------------------------------------------------------
// mma.sync GEMM: C = A * W^T + bias [+ReLU] [+res]; out fp32 or bf16 hi/lo
// 128x128 CTA tile, BK=64, 3-stage cp.async pipeline, 1 barrier per chunk.
// ---------------------------------------------------------------------------
#define TILE_B   16384
#define STAGE_B  (4 * TILE_B)
#define MMG_SMEM (3 * STAGE_B)          // 196608

__device__ __forceinline__ uint32_t swadr(uint32_t tbase, int row, int chunk) {
    return tbase + row * 128 + (((chunk ^ row) & 7) << 4) + ((chunk & ~7) << 4);
}

__global__ void __launch_bounds__(256, 1)
mm_gemm(const __nv_bfloat16* __restrict__ Ahi, const __nv_bfloat16* __restrict__ Alo,
        const __nv_bfloat16* __restrict__ Whi, const __nv_bfloat16* __restrict__ Wlo,
        const float* __restrict__ bias, const float* __restrict__ res,
        float* __restrict__ Cf, __nv_bfloat16* __restrict__ Chi,
        __nv_bfloat16* __restrict__ Clo, int doRelu)
{
    extern __shared__ char smem[];
    const uint32_t sb = smem_u32(smem);
    const int tid = threadIdx.x;
    const int wid = tid >> 5;
    const int lid = tid & 31;
    const int warpM = wid >> 2;
    const int warpN = wid & 3;
    const int bn = blockIdx.x * 128;
    const int bm = blockIdx.y * 128;

    const __nv_bfloat16* baseA0 = Ahi + (size_t)bm * 1024;
    const __nv_bfloat16* baseA1 = Alo + (size_t)bm * 1024;
    const __nv_bfloat16* baseW0 = Whi + (size_t)bn * 1024;
    const __nv_bfloat16* baseW1 = Wlo + (size_t)bn * 1024;

    #define LOAD_CHUNK(stg, k0) do {                                              \
        const uint32_t _sbase = sb + (stg) * STAGE_B;                             \
        _Pragma("unroll")                                                         \
        for (int i = 0; i < 16; i++) {                                            \
            const int tile = i >> 2;                                              \
            const int idx  = (tid + i * 256) & 1023;                              \
            const int r    = idx >> 3;                                            \
            const int c8   = idx & 7;                                             \
            const __nv_bfloat16* gp =                                             \
                (tile == 0 ? baseA0 : tile == 1 ? baseA1 :                        \
                 tile == 2 ? baseW0 : baseW1) + (size_t)r * 1024 + (k0) + c8 * 8; \
            const uint32_t sa = _sbase + tile * TILE_B +                          \
                (uint32_t)(r * 128 + (((c8 ^ r) & 7) << 4));                      \
            CP_ASYNC16(sa, gp);                                                   \
        }                                                                         \
        CP_COMMIT();                                                              \
    } while (0)

    float acc[4][4][4];
    #pragma unroll
    for (int a = 0; a < 4; a++)
        #pragma unroll
        for (int b = 0; b < 4; b++)
            #pragma unroll
            for (int c = 0; c < 4; c++) acc[a][b][c] = 0.f;

    const int aRow = warpM * 64 + (lid & 15);
    const int aChk = lid >> 4;
    const int bRow = warpN * 32 + ((lid >= 16) ? 8 : 0) + (lid & 7);
    const int bChk = (lid >> 3) & 1;

    LOAD_CHUNK(0, 0);
    LOAD_CHUNK(1, 64);

    #pragma unroll 1
    for (int c = 0; c < 16; c++) {
        if (c == 15) CP_WAIT0(); else CP_WAIT1();
        __syncthreads();
        if (c + 2 < 16) LOAD_CHUNK((c + 2) % 3, (c + 2) * 64);

        const int s = c % 3;
        const uint32_t sA0 = sb + s * STAGE_B;
        const uint32_t sA1 = sA0 + TILE_B;
        const uint32_t sW0 = sA0 + 2 * TILE_B;
        const uint32_t sW1 = sA0 + 3 * TILE_B;

        #pragma unroll
        for (int s16 = 0; s16 < 4; s16++) {
            const int kc = s16 * 2;
            uint32_t Bh[4][2], Bl[4][2];
            #pragma unroll
            for (int pair = 0; pair < 2; pair++) {
                const int r = bRow + pair * 16;
                ldsm4(&Bh[pair * 2][0], swadr(sW0, r, kc + bChk));
                ldsm4(&Bl[pair * 2][0], swadr(sW1, r, kc + bChk));
            }
            #pragma unroll
            for (int mt = 0; mt < 4; mt++) {
                uint32_t Ah[4], Al[4];
                const int r = aRow + mt * 16;
                ldsm4(Ah, swadr(sA0, r, kc + aChk));
                ldsm4(Al, swadr(sA1, r, kc + aChk));
                #pragma unroll
                for (int nt = 0; nt < 4; nt++) {
                    mma_bf16(acc[mt][nt], Ah, Bh[nt]);
                    mma_bf16(acc[mt][nt], Ah, Bl[nt]);
                    mma_bf16(acc[mt][nt], Al, Bh[nt]);
                }
            }
        }
    }

    const int rowoff = lid >> 2;
    const int coloff = (lid & 3) * 2;
    #pragma unroll
    for (int mt = 0; mt < 4; mt++) {
        #pragma unroll
        for (int nt = 0; nt < 4; nt++) {
            const int gn = bn + warpN * 32 + nt * 8 + coloff;
            const float b0 = __ldg(&bias[gn]);
            const float b1 = __ldg(&bias[gn + 1]);
            #pragma unroll
            for (int half = 0; half < 2; half++) {
                const int gm = bm + warpM * 64 + mt * 16 + rowoff + half * 8;
                float v0 = acc[mt][nt][half * 2 + 0] + b0;
                float v1 = acc[mt][nt][half * 2 + 1] + b1;
                if (doRelu) { v0 = fmaxf(v0, 0.f); v1 = fmaxf(v1, 0.f); }
                const size_t off = (size_t)gm * 1024 + gn;
                if (res) {
                    const float2 rv = *(const float2*)&res[off];
                    v0 += rv.x; v1 += rv.y;
                }
                if (Cf) {
                    *(float2*)&Cf[off] = make_float2(v0, v1);
                } else {
                    uint32_t h, l;
                    split2(v0, v1, h, l);
                    *(uint32_t*)&Chi[off] = h;
                    *(uint32_t*)&Clo[off] = l;
                }
            }
        }
    }
}

// ---------------------------------------------------------------------------
// Flash attention on mma.sync. QK^T uses bf16x3; P*V uses Phi*(Vhi+Vlo)
// (P in [0,1]; its lo-term contributes ~4e-5 rel — dropped).
// Per CTA: one (b,h), 128 queries, 8 warps x 16 rows. 64-key tiles,
// 3-stage cp.async pipeline, one barrier per tile.
// ---------------------------------------------------------------------------
#define AQ 128
#define AK 64
#define ATT_Q    0
#define ATT_ST   32768
#define ATT_STB  32768
#define ATT_SMEM (ATT_ST + 3 * ATT_STB)   // 131072

__global__ void __launch_bounds__(256, 1) attn_mma(
    const __nv_bfloat16* __restrict__ Qhi, const __nv_bfloat16* __restrict__ Qlo,
    const __nv_bfloat16* __restrict__ Khi, const __nv_bfloat16* __restrict__ Klo,
    const __nv_bfloat16* __restrict__ Vhi, const __nv_bfloat16* __restrict__ Vlo,
    __nv_bfloat16* __restrict__ Ohi, __nv_bfloat16* __restrict__ Olo)
{
    extern __shared__ char smem[];
    const uint32_t sb = smem_u32(smem);
    const int tid = threadIdx.x;
    const int wid = tid >> 5;
    const int lid = tid & 31;
    const int bh  = blockIdx.y;
    const int b   = bh >> 4;
    const int h   = bh & 15;
    const int q0  = blockIdx.x * AQ;
    const size_t rowBase = (size_t)b * SEQ;
    const int hcol = h * HDIM;

    // ---- Q load (group 0) ----
    {
        #pragma unroll
        for (int i = 0; i < 8; i++) {
            const int tile = i >> 2;
            const int idx  = (tid + i * 256) & 1023;
            const int r    = idx >> 3;
            const int c8   = idx & 7;
            const __nv_bfloat16* gp = (tile ? Qlo : Qhi)
                + (rowBase + q0 + r) * 1024 + hcol + c8 * 8;
            const uint32_t sa = sb + ATT_Q + tile * 16384
                + (uint32_t)(r * 128 + (((c8 ^ r) & 7) << 4));
            CP_ASYNC16(sa, gp);
        }
        CP_COMMIT();
    }

    #define LOAD_KV(stg, kt) do {                                               \
        const uint32_t _sbase = sb + ATT_ST + (stg) * ATT_STB;                  \
        _Pragma("unroll")                                                       \
        for (int i = 0; i < 8; i++) {                                           \
            const int tile = i >> 1;                                            \
            const int idx  = (tid + (i & 1) * 256) & 511;                       \
            const int r    = idx >> 3;                                          \
            const int c8   = idx & 7;                                           \
            const __nv_bfloat16* gp =                                           \
                (tile == 0 ? Khi : tile == 1 ? Klo : tile == 2 ? Vhi : Vlo)     \
                + (rowBase + (kt) * AK + r) * 1024 + hcol + c8 * 8;             \
            const uint32_t sa = _sbase + tile * 8192 +                          \
                (uint32_t)(r * 128 + (((c8 ^ r) & 7) << 4));                    \
            CP_ASYNC16(sa, gp);                                                 \
        }                                                                       \
        CP_COMMIT();                                                            \
    } while (0)

    LOAD_KV(0, 0);
    LOAD_KV(1, 1);
    CP_WAIT1();                 // Q + KV0 complete
    __syncthreads();

    // ---- persistent Q fragments ----
    uint32_t Qh[4][4], Ql[4][4];
    {
        const int r = wid * 16 + (lid & 15);
        const int ck = lid >> 4;
        #pragma unroll
        for (int t = 0; t < 4; t++) {
            ldsm4(Qh[t], swadr(sb + ATT_Q,         r, 2 * t + ck));
            ldsm4(Ql[t], swadr(sb + ATT_Q + 16384, r, 2 * t + ck));
        }
    }

    float o[8][4];
    #pragma unroll
    for (int j = 0; j < 8; j++)
        #pragma unroll
        for (int e = 0; e < 4; e++) o[j][e] = 0.f;
    float m0 = -INFINITY, m1 = -INFINITY, l0 = 0.f, l1 = 0.f;
    const float cs = 0.125f * 1.4426950408889634f;

    const int kRowL = ((lid >= 16) ? 8 : 0) + (lid & 7);
    const int kChkL = (lid >> 3) & 1;
    const int vT    = lid >> 3;
    const int vKeyL = ((vT & 1) << 3) + (lid & 7);
    const int vChkL = vT >> 1;

    #pragma unroll 1
    for (int kt = 0; kt < SEQ / AK; kt++) {
        if (kt > 0) {
            if (kt == SEQ / AK - 1) CP_WAIT0(); else CP_WAIT1();
            __syncthreads();
        }
        if (kt + 2 < SEQ / AK) LOAD_KV((kt + 2) % 3, kt + 2);

        const uint32_t sKh = sb + ATT_ST + (kt % 3) * ATT_STB;
        const uint32_t sKl = sKh + 8192;
        const uint32_t sVh = sKh + 16384;
        const uint32_t sVl = sKh + 24576;

        // ---- S = Q K^T (bf16x3) ----
        float sc[8][4];
        #pragma unroll
        for (int j = 0; j < 8; j++)
            #pragma unroll
            for (int e = 0; e < 4; e++) sc[j][e] = 0.f;

        #pragma unroll
        for (int t = 0; t < 4; t++) {
            #pragma unroll
            for (int kp = 0; kp < 4; kp++) {
                uint32_t kh[4], kl[4];
                const int r = kp * 16 + kRowL;
                ldsm4(kh, swadr(sKh, r, 2 * t + kChkL));
                ldsm4(kl, swadr(sKl, r, 2 * t + kChkL));
                mma_bf16(sc[2 * kp],     Qh[t], kh);
                mma_bf16(sc[2 * kp + 1], Qh[t], kh + 2);
                mma_bf16(sc[2 * kp],     Qh[t], kl);
                mma_bf16(sc[2 * kp + 1], Qh[t], kl + 2);
                mma_bf16(sc[2 * kp],     Ql[t], kh);
                mma_bf16(sc[2 * kp + 1], Ql[t], kh + 2);
            }
        }

        // ---- online softmax ----
        float mx0 = -INFINITY, mx1 = -INFINITY;
        #pragma unroll
        for (int j = 0; j < 8; j++) {
            mx0 = fmaxf(mx0, fmaxf(sc[j][0], sc[j][1]));
            mx1 = fmaxf(mx1, fmaxf(sc[j][2], sc[j][3]));
        }
        mx0 *= cs; mx1 *= cs;
        #pragma unroll
        for (int d = 1; d < 4; d <<= 1) {
            mx0 = fmaxf(mx0, __shfl_xor_sync(0xffffffffu, mx0, d));
            mx1 = fmaxf(mx1, __shfl_xor_sync(0xffffffffu, mx1, d));
        }
        const float m0n = fmaxf(m0, mx0);
        const float m1n = fmaxf(m1, mx1);
        float sc0, sc1;
        EX2(sc0, m0 - m0n);
        EX2(sc1, m1 - m1n);
        m0 = m0n; m1 = m1n;

        float rs0 = 0.f, rs1 = 0.f;
        uint32_t ph01[8], ph23[8];
        #pragma unroll
        for (int j = 0; j < 8; j++) {
            float p00, p01, p10, p11;
            EX2(p00, fmaf(sc[j][0], cs, -m0));
            EX2(p01, fmaf(sc[j][1], cs, -m0));
            EX2(p10, fmaf(sc[j][2], cs, -m1));
            EX2(p11, fmaf(sc[j][3], cs, -m1));
            rs0 += p00 + p01;
            rs1 += p10 + p11;
            PACK_BF16X2(ph01[j], p00, p01);
            PACK_BF16X2(ph23[j], p10, p11);
        }
        #pragma unroll
        for (int d = 1; d < 4; d <<= 1) {
            rs0 += __shfl_xor_sync(0xffffffffu, rs0, d);
            rs1 += __shfl_xor_sync(0xffffffffu, rs1, d);
        }
        l0 = l0 * sc0 + rs0;
        l1 = l1 * sc1 + rs1;
        #pragma unroll
        for (int j = 0; j < 8; j++) {
            o[j][0] *= sc0; o[j][1] *= sc0;
            o[j][2] *= sc1; o[j][3] *= sc1;
        }

        // ---- O += Phi * (Vhi + Vlo) ----
        #pragma unroll
        for (int kb = 0; kb < 4; kb++) {
            const uint32_t pa_h[4] = { ph01[2 * kb], ph23[2 * kb],
                                       ph01[2 * kb + 1], ph23[2 * kb + 1] };
            #pragma unroll
            for (int np = 0; np < 4; np++) {
                uint32_t vh[4], vl[4];
                const int key = kb * 16 + vKeyL;
                const int ck  = np * 2 + vChkL;
                ldsm4t(vh, swadr(sVh, key, ck));
                ldsm4t(vl, swadr(sVl, key, ck));
                mma_bf16(o[2 * np],     pa_h, vh);
                mma_bf16(o[2 * np + 1], pa_h, vh + 2);
                mma_bf16(o[2 * np],     pa_h, vl);
                mma_bf16(o[2 * np + 1], pa_h, vl + 2);
            }
        }
    }

    // ---- epilogue ----
    const float il0 = 1.0f / l0;
    const float il1 = 1.0f / l1;
    const size_t row0 = rowBase + q0 + wid * 16 + (lid >> 2);
    const size_t row1 = row0 + 8;
    const int cb = hcol + (lid & 3) * 2;
    #pragma unroll
    for (int j = 0; j < 8; j++) {
        const int col = cb + j * 8;
        uint32_t h, l;
        split2(o[j][0] * il0, o[j][1] * il0, h, l);
        *(uint32_t*)&Ohi[row0 * 1024 + col] = h;
        *(uint32_t*)&Olo[row0 * 1024 + col] = l;
        split2(o[j][2] * il1, o[j][3] * il1, h, l);
        *(uint32_t*)&Ohi[row1 * 1024 + col] = h;
        *(uint32_t*)&Olo[row1 * 1024 + col] = l;
    }
}

// ---------------------------------------------------------------------------
// Launch
// ---------------------------------------------------------------------------
extern "C" void kernel_launch(void* const* d_in, const int* in_sizes, int n_in,
                              void* d_out, int out_size)
{
    const float* src = (const float*)d_in[0];
    const float* Wq  = (const float*)d_in[1];  const float* bq = (const float*)d_in[2];
    const float* Wk  = (const float*)d_in[3];  const float* bk = (const float*)d_in[4];
    const float* Wv  = (const float*)d_in[5];  const float* bv = (const float*)d_in[6];
    const float* Wo  = (const float*)d_in[7];  const float* bo = (const float*)d_in[8];
    const float* W1  = (const float*)d_in[9];  const float* b1 = (const float*)d_in[10];
    const float* W2  = (const float*)d_in[11]; const float* b2 = (const float*)d_in[12];
    const float* g1  = (const float*)d_in[13]; const float* be1 = (const float*)d_in[14];
    const float* g2  = (const float*)d_in[15]; const float* be2 = (const float*)d_in[16];
    float* out = (float*)d_out;

    float* x1;
    __nv_bfloat16 *ahi, *alo, *whi, *wlo, *qhi, *qlo, *khi, *klo, *vhi, *vlo;
    cudaGetSymbolAddress((void**)&x1,  g_x1);
    cudaGetSymbolAddress((void**)&ahi, g_ahi);
    cudaGetSymbolAddress((void**)&alo, g_alo);
    cudaGetSymbolAddress((void**)&whi, g_whi);
    cudaGetSymbolAddress((void**)&wlo, g_wlo);
    cudaGetSymbolAddress((void**)&qhi, g_qhi);
    cudaGetSymbolAddress((void**)&qlo, g_qlo);
    cudaGetSymbolAddress((void**)&khi, g_khi);
    cudaGetSymbolAddress((void**)&klo, g_klo);
    cudaGetSymbolAddress((void**)&vhi, g_vhi);
    cudaGetSymbolAddress((void**)&vlo, g_vlo);

    cudaFuncSetAttribute(mm_gemm,  cudaFuncAttributeMaxDynamicSharedMemorySize, MMG_SMEM);
    cudaFuncSetAttribute(attn_mma, cudaFuncAttributeMaxDynamicSharedMemorySize, ATT_SMEM);

    const int WN = D_MODEL * D_MODEL;                // elements per weight
    const dim3 gGemm(D_MODEL / 128, M_TOTAL / 128);  // (8, 64)
    const dim3 gAttn(SEQ / AQ, BATCH * NHEADS);      // (16, 64)
    const dim3 gWs(WN / 4 / 256, 6);                 // (1024, 6)

    // all weight splits once; ln1(src) -> bf16 split
    wsplit6_kernel<<<gWs, 256>>>(Wq, Wk, Wv, Wo, W1, W2, whi, wlo);
    ln_split_kernel<<<M_TOTAL, 256>>>(src, g1, be1, ahi, alo);

    // Q/K/V projections (bf16 hi/lo out)
    mm_gemm<<<gGemm, 256, MMG_SMEM>>>(ahi, alo, whi + 0 * WN, wlo + 0 * WN, bq,
                                      nullptr, nullptr, qhi, qlo, 0);
    mm_gemm<<<gGemm, 256, MMG_SMEM>>>(ahi, alo, whi + 1 * WN, wlo + 1 * WN, bk,
                                      nullptr, nullptr, khi, klo, 0);
    mm_gemm<<<gGemm, 256, MMG_SMEM>>>(ahi, alo, whi + 2 * WN, wlo + 2 * WN, bv,
                                      nullptr, nullptr, vhi, vlo, 0);

    // attention -> bf16 hi/lo
    attn_mma<<<gAttn, 256, ATT_SMEM>>>(qhi, qlo, khi, klo, vhi, vlo, ahi, alo);

    // x1 = src + att @ Wo^T + bo   (fp32 out)
    mm_gemm<<<gGemm, 256, MMG_SMEM>>>(ahi, alo, whi + 3 * WN, wlo + 3 * WN, bo,
                                      src, x1, nullptr, nullptr, 0);

    // ln2(x1) -> bf16; h1 = relu(... @ W1^T + b1) (bf16 out)
    ln_split_kernel<<<M_TOTAL, 256>>>(x1, g2, be2, ahi, alo);
    mm_gemm<<<gGemm, 256, MMG_SMEM>>>(ahi, alo, whi + 4 * WN, wlo + 4 * WN, b1,
                                      nullptr, nullptr, qhi, qlo, 1);

    // out = x1 + h1 @ W2^T + b2
    mm_gemm<<<gGemm, 256, MMG_SMEM>>>(qhi, qlo, whi + 5 * WN, wlo + 5 * WN, b2,
                                      x1, out, nullptr, nullptr, 0);
}

// round 6
// speedup vs baseline: 6.0525x; 1.7048x over previous
#include <cuda_runtime.h>
#include <cuda_fp16.h>
#include <math.h>
#include <stdint.h>

#define D_MODEL 1024
#define SEQ     2048
#define BATCH   4
#define NHEADS  16
#define HDIM    64
#define M_TOTAL (BATCH * SEQ)      // 8192
#define LN_EPS  1e-5f

// ---------------------------------------------------------------------------
// Scratch buffers (allocation-free rule: __device__ globals)
// ---------------------------------------------------------------------------
__device__ float  g_x1 [M_TOTAL * D_MODEL];
__device__ __half g_a  [M_TOTAL * D_MODEL];    // activations (LN out / att out)
__device__ __half g_q  [M_TOTAL * D_MODEL];
__device__ __half g_k  [M_TOTAL * D_MODEL];
__device__ __half g_v  [M_TOTAL * D_MODEL];
__device__ __half g_h1 [M_TOTAL * D_MODEL];
__device__ __half g_whi[6 * D_MODEL * D_MODEL];
__device__ __half g_wlo[6 * D_MODEL * D_MODEL];

// ---------------------------------------------------------------------------
// Helpers (sm_80+ ISA: mma.sync / ldmatrix / cp.async)
// ---------------------------------------------------------------------------
__device__ __forceinline__ uint32_t smem_u32(const void* p) {
    uint32_t a;
    asm("{ .reg .u64 t; cvta.to.shared.u64 t, %1; cvt.u32.u64 %0, t; }" : "=r"(a) : "l"(p));
    return a;
}
#define CP_ASYNC16(sa, g) \
    asm volatile("cp.async.cg.shared.global [%0], [%1], 16;" :: "r"(sa), "l"(g) : "memory")
#define CP_COMMIT() asm volatile("cp.async.commit_group;" ::: "memory")
#define CP_WAIT0()  asm volatile("cp.async.wait_group 0;" ::: "memory")
#define CP_WAIT1()  asm volatile("cp.async.wait_group 1;" ::: "memory")

__device__ __forceinline__ void ldsm4(uint32_t* r, uint32_t addr) {
    asm volatile("ldmatrix.sync.aligned.m8n8.x4.shared.b16 {%0,%1,%2,%3}, [%4];"
                 : "=r"(r[0]), "=r"(r[1]), "=r"(r[2]), "=r"(r[3]) : "r"(addr));
}
__device__ __forceinline__ void ldsm4t(uint32_t* r, uint32_t addr) {
    asm volatile("ldmatrix.sync.aligned.m8n8.x4.trans.shared.b16 {%0,%1,%2,%3}, [%4];"
                 : "=r"(r[0]), "=r"(r[1]), "=r"(r[2]), "=r"(r[3]) : "r"(addr));
}
__device__ __forceinline__ void mma_f16(float* d, const uint32_t* a, const uint32_t* b) {
    asm volatile("mma.sync.aligned.m16n8k16.row.col.f32.f16.f16.f32 "
                 "{%0,%1,%2,%3}, {%4,%5,%6,%7}, {%8,%9}, {%0,%1,%2,%3};"
                 : "+f"(d[0]), "+f"(d[1]), "+f"(d[2]), "+f"(d[3])
                 : "r"(a[0]), "r"(a[1]), "r"(a[2]), "r"(a[3]), "r"(b[0]), "r"(b[1]));
}
#define EX2(d, x) asm("ex2.approx.ftz.f32 %0, %1;" : "=f"(d) : "f"(x))

__device__ __forceinline__ uint32_t packh2(float v0, float v1) {
    __half2 t = __floats2half2_rn(v0, v1);
    return *(uint32_t*)&t;
}

// ---------------------------------------------------------------------------
// All six weight splits (fp16 hi/lo) in one launch
// ---------------------------------------------------------------------------
__global__ void __launch_bounds__(256) wsplit6_kernel(
    const float* __restrict__ w0, const float* __restrict__ w1,
    const float* __restrict__ w2, const float* __restrict__ w3,
    const float* __restrict__ w4, const float* __restrict__ w5,
    __half* __restrict__ hi, __half* __restrict__ lo)
{
    const int ws = blockIdx.y;
    const float* src = (ws == 0) ? w0 : (ws == 1) ? w1 : (ws == 2) ? w2
                     : (ws == 3) ? w3 : (ws == 4) ? w4 : w5;
    const int i = blockIdx.x * 256 + threadIdx.x;
    const float4 v = ((const float4*)src)[i];
    const __half2 h0 = __floats2half2_rn(v.x, v.y);
    const __half2 h1 = __floats2half2_rn(v.z, v.w);
    const __half2 l0 = __floats2half2_rn(v.x - __half2float(__low2half(h0)),
                                         v.y - __half2float(__high2half(h0)));
    const __half2 l1 = __floats2half2_rn(v.z - __half2float(__low2half(h1)),
                                         v.w - __half2float(__high2half(h1)));
    const size_t base = (size_t)ws * (D_MODEL * D_MODEL / 2) + 2 * i;
    ((__half2*)hi)[base] = h0; ((__half2*)hi)[base + 1] = h1;
    ((__half2*)lo)[base] = l0; ((__half2*)lo)[base + 1] = l1;
}

// ---------------------------------------------------------------------------
// Fused LayerNorm -> single fp16
// ---------------------------------------------------------------------------
__global__ void __launch_bounds__(256) ln_half_kernel(
    const float* __restrict__ x, const float* __restrict__ g,
    const float* __restrict__ b, __half* __restrict__ y)
{
    __shared__ float red[16];
    const int row = blockIdx.x;
    const int tid = threadIdx.x;
    const float4 v = ((const float4*)(x + (size_t)row * D_MODEL))[tid];

    float s  = v.x + v.y + v.z + v.w;
    float ss = v.x * v.x + v.y * v.y + v.z * v.z + v.w * v.w;
    #pragma unroll
    for (int o = 16; o; o >>= 1) {
        s  += __shfl_xor_sync(0xffffffffu, s,  o);
        ss += __shfl_xor_sync(0xffffffffu, ss, o);
    }
    const int wid = tid >> 5;
    if ((tid & 31) == 0) { red[wid] = s; red[8 + wid] = ss; }
    __syncthreads();
    float S = 0.f, SS = 0.f;
    #pragma unroll
    for (int w = 0; w < 8; w++) { S += red[w]; SS += red[8 + w]; }
    const float mu   = S * (1.0f / D_MODEL);
    const float var  = SS * (1.0f / D_MODEL) - mu * mu;
    const float rstd = rsqrtf(var + LN_EPS);

    const float4 gv = ((const float4*)g)[tid];
    const float4 bv = ((const float4*)b)[tid];
    const float o0 = (v.x - mu) * rstd * gv.x + bv.x;
    const float o1 = (v.y - mu) * rstd * gv.y + bv.y;
    const float o2 = (v.z - mu) * rstd * gv.z + bv.z;
    const float o3 = (v.w - mu) * rstd * gv.w + bv.w;
    const size_t base = (size_t)row * (D_MODEL / 2) + tid * 2;
    ((uint32_t*)y)[base]     = packh2(o0, o1);
    ((uint32_t*)y)[base + 1] = packh2(o2, o3);
}

// ---------------------------------------------------------------------------
// fp16 GEMM: C = A * W^T + bias [+ReLU] [+res]; A single fp16, W hi+lo.
// 128x128 CTA tile, BK=64, 2-stage cp.async, 2 CTAs/SM target.
// ---------------------------------------------------------------------------
#define TILE_B   16384                  // 128 rows x 64 fp16 x 2B
#define STAGE_B  (3 * TILE_B)           // A, Whi, Wlo = 48KB
#define MMG_SMEM (2 * STAGE_B)          // 98304

__device__ __forceinline__ uint32_t swadr(uint32_t tbase, int row, int chunk) {
    return tbase + row * 128 + (((chunk ^ row) & 7) << 4) + ((chunk & ~7) << 4);
}

__global__ void __launch_bounds__(256, 2)
mm_gemm(const __half* __restrict__ A,
        const __half* __restrict__ Whi, const __half* __restrict__ Wlo,
        const float* __restrict__ bias, const float* __restrict__ res,
        float* __restrict__ Cf, __half* __restrict__ Ch, int doRelu)
{
    extern __shared__ char smem[];
    const uint32_t sb = smem_u32(smem);
    const int tid = threadIdx.x;
    const int wid = tid >> 5;
    const int lid = tid & 31;
    const int warpM = wid >> 2;
    const int warpN = wid & 3;
    const int bn = blockIdx.x * 128;
    const int bm = blockIdx.y * 128;

    const __half* baseA  = A   + (size_t)bm * 1024;
    const __half* baseW0 = Whi + (size_t)bn * 1024;
    const __half* baseW1 = Wlo + (size_t)bn * 1024;

    // 3072 x 16B chunks per stage; 12 per thread
    #define LOAD_CHUNK(stg, k0) do {                                              \
        const uint32_t _sbase = sb + (stg) * STAGE_B;                             \
        _Pragma("unroll")                                                         \
        for (int i = 0; i < 12; i++) {                                            \
            const int tile = i >> 2;                                              \
            const int idx  = (tid + i * 256) & 1023;                              \
            const int r    = idx >> 3;                                            \
            const int c8   = idx & 7;                                             \
            const __half* gp =                                                    \
                (tile == 0 ? baseA : tile == 1 ? baseW0 : baseW1)                 \
                + (size_t)r * 1024 + (k0) + c8 * 8;                               \
            const uint32_t sa = _sbase + tile * TILE_B +                          \
                (uint32_t)(r * 128 + (((c8 ^ r) & 7) << 4));                      \
            CP_ASYNC16(sa, gp);                                                   \
        }                                                                         \
        CP_COMMIT();                                                              \
    } while (0)

    float acc[4][4][4];
    #pragma unroll
    for (int a = 0; a < 4; a++)
        #pragma unroll
        for (int b = 0; b < 4; b++)
            #pragma unroll
            for (int c = 0; c < 4; c++) acc[a][b][c] = 0.f;

    const int aRow = warpM * 64 + (lid & 15);
    const int aChk = lid >> 4;
    const int bRow = warpN * 32 + ((lid >= 16) ? 8 : 0) + (lid & 7);
    const int bChk = (lid >> 3) & 1;

    LOAD_CHUNK(0, 0);

    #pragma unroll 1
    for (int c = 0; c < 16; c++) {
        const int s = c & 1;
        __syncthreads();
        if (c < 15) { LOAD_CHUNK(s ^ 1, (c + 1) * 64); CP_WAIT1(); }
        else        { CP_WAIT0(); }
        __syncthreads();

        const uint32_t sA  = sb + s * STAGE_B;
        const uint32_t sW0 = sA + TILE_B;
        const uint32_t sW1 = sA + 2 * TILE_B;

        #pragma unroll
        for (int s16 = 0; s16 < 4; s16++) {
            const int kc = s16 * 2;
            uint32_t Bh[4][2], Bl[4][2];
            #pragma unroll
            for (int pair = 0; pair < 2; pair++) {
                const int r = bRow + pair * 16;
                ldsm4(&Bh[pair * 2][0], swadr(sW0, r, kc + bChk));
                ldsm4(&Bl[pair * 2][0], swadr(sW1, r, kc + bChk));
            }
            #pragma unroll
            for (int mt = 0; mt < 4; mt++) {
                uint32_t Af[4];
                ldsm4(Af, swadr(sA, aRow + mt * 16, kc + aChk));
                #pragma unroll
                for (int nt = 0; nt < 4; nt++) {
                    mma_f16(acc[mt][nt], Af, Bh[nt]);
                    mma_f16(acc[mt][nt], Af, Bl[nt]);
                }
            }
        }
    }

    const int rowoff = lid >> 2;
    const int coloff = (lid & 3) * 2;
    #pragma unroll
    for (int mt = 0; mt < 4; mt++) {
        #pragma unroll
        for (int nt = 0; nt < 4; nt++) {
            const int gn = bn + warpN * 32 + nt * 8 + coloff;
            const float b0 = __ldg(&bias[gn]);
            const float b1 = __ldg(&bias[gn + 1]);
            #pragma unroll
            for (int half = 0; half < 2; half++) {
                const int gm = bm + warpM * 64 + mt * 16 + rowoff + half * 8;
                float v0 = acc[mt][nt][half * 2 + 0] + b0;
                float v1 = acc[mt][nt][half * 2 + 1] + b1;
                if (doRelu) { v0 = fmaxf(v0, 0.f); v1 = fmaxf(v1, 0.f); }
                const size_t off = (size_t)gm * 1024 + gn;
                if (res) {
                    const float2 rv = *(const float2*)&res[off];
                    v0 += rv.x; v1 += rv.y;
                }
                if (Cf) *(float2*)&Cf[off] = make_float2(v0, v1);
                else    *(uint32_t*)&Ch[off] = packh2(v0, v1);
            }
        }
    }
}

// ---------------------------------------------------------------------------
// Flash attention, single-term fp16 MMA. Per CTA: one (b,h), 128 queries,
// 8 warps x 16 rows, 64-key tiles, 3-stage cp.async. 2 CTAs/SM target.
// smem: Q 16KB | 3 stages x (K 8KB + V 8KB)
// ---------------------------------------------------------------------------
#define AQ 128
#define AK 64
#define ATT_ST   16384
#define ATT_STB  16384
#define ATT_SMEM (ATT_ST + 3 * ATT_STB)   // 65536

__global__ void __launch_bounds__(256, 2) attn_mma(
    const __half* __restrict__ Q, const __half* __restrict__ K,
    const __half* __restrict__ V, __half* __restrict__ O)
{
    extern __shared__ char smem[];
    const uint32_t sb = smem_u32(smem);
    const int tid = threadIdx.x;
    const int wid = tid >> 5;
    const int lid = tid & 31;
    const int bh  = blockIdx.y;
    const int b   = bh >> 4;
    const int h   = bh & 15;
    const int q0  = blockIdx.x * AQ;
    const size_t rowBase = (size_t)b * SEQ;
    const int hcol = h * HDIM;

    // ---- Q load: 1024 chunks, 4/thread ----
    {
        #pragma unroll
        for (int i = 0; i < 4; i++) {
            const int idx = tid + i * 256;           // 0..1023
            const int r   = idx >> 3;
            const int c8  = idx & 7;
            const __half* gp = Q + (rowBase + q0 + r) * 1024 + hcol + c8 * 8;
            const uint32_t sa = sb + (uint32_t)(r * 128 + (((c8 ^ r) & 7) << 4));
            CP_ASYNC16(sa, gp);
        }
        CP_COMMIT();
    }

    #define LOAD_KV(stg, kt) do {                                               \
        const uint32_t _sbase = sb + ATT_ST + (stg) * ATT_STB;                  \
        _Pragma("unroll")                                                       \
        for (int i = 0; i < 4; i++) {                                           \
            const int tile = i >> 1;                                            \
            const int idx  = (tid + (i & 1) * 256) & 511;                       \
            const int r    = idx >> 3;                                          \
            const int c8   = idx & 7;                                           \
            const __half* gp = (tile ? V : K)                                   \
                + (rowBase + (kt) * AK + r) * 1024 + hcol + c8 * 8;             \
            const uint32_t sa = _sbase + tile * 8192 +                          \
                (uint32_t)(r * 128 + (((c8 ^ r) & 7) << 4));                    \
            CP_ASYNC16(sa, gp);                                                 \
        }                                                                       \
        CP_COMMIT();                                                            \
    } while (0)

    LOAD_KV(0, 0);
    LOAD_KV(1, 1);
    CP_WAIT1();                 // Q + KV0 complete
    __syncthreads();

    // ---- persistent Q fragments ----
    uint32_t Qf[4][4];
    {
        const int r = wid * 16 + (lid & 15);
        const int ck = lid >> 4;
        #pragma unroll
        for (int t = 0; t < 4; t++) ldsm4(Qf[t], swadr(sb, r, 2 * t + ck));
    }

    float o[8][4];
    #pragma unroll
    for (int j = 0; j < 8; j++)
        #pragma unroll
        for (int e = 0; e < 4; e++) o[j][e] = 0.f;
    float m0 = -INFINITY, m1 = -INFINITY, l0 = 0.f, l1 = 0.f;
    const float cs = 0.125f * 1.4426950408889634f;

    const int kRowL = ((lid >= 16) ? 8 : 0) + (lid & 7);
    const int kChkL = (lid >> 3) & 1;
    const int vT    = lid >> 3;
    const int vKeyL = ((vT & 1) << 3) + (lid & 7);
    const int vChkL = vT >> 1;

    #pragma unroll 1
    for (int kt = 0; kt < SEQ / AK; kt++) {
        if (kt > 0) {
            if (kt == SEQ / AK - 1) CP_WAIT0(); else CP_WAIT1();
            __syncthreads();
        }
        if (kt + 2 < SEQ / AK) LOAD_KV((kt + 2) % 3, kt + 2);

        const uint32_t sK = sb + ATT_ST + (kt % 3) * ATT_STB;
        const uint32_t sV = sK + 8192;

        // ---- S = Q K^T (single fp16 term) ----
        float sc[8][4];
        #pragma unroll
        for (int j = 0; j < 8; j++)
            #pragma unroll
            for (int e = 0; e < 4; e++) sc[j][e] = 0.f;

        #pragma unroll
        for (int t = 0; t < 4; t++) {
            #pragma unroll
            for (int kp = 0; kp < 4; kp++) {
                uint32_t kf[4];
                ldsm4(kf, swadr(sK, kp * 16 + kRowL, 2 * t + kChkL));
                mma_f16(sc[2 * kp],     Qf[t], kf);
                mma_f16(sc[2 * kp + 1], Qf[t], kf + 2);
            }
        }

        // ---- online softmax ----
        float mx0 = -INFINITY, mx1 = -INFINITY;
        #pragma unroll
        for (int j = 0; j < 8; j++) {
            mx0 = fmaxf(mx0, fmaxf(sc[j][0], sc[j][1]));
            mx1 = fmaxf(mx1, fmaxf(sc[j][2], sc[j][3]));
        }
        mx0 *= cs; mx1 *= cs;
        #pragma unroll
        for (int d = 1; d < 4; d <<= 1) {
            mx0 = fmaxf(mx0, __shfl_xor_sync(0xffffffffu, mx0, d));
            mx1 = fmaxf(mx1, __shfl_xor_sync(0xffffffffu, mx1, d));
        }
        const float m0n = fmaxf(m0, mx0);
        const float m1n = fmaxf(m1, mx1);
        float sc0, sc1;
        EX2(sc0, m0 - m0n);
        EX2(sc1, m1 - m1n);
        m0 = m0n; m1 = m1n;

        float rs0 = 0.f, rs1 = 0.f;
        uint32_t ph01[8], ph23[8];
        #pragma unroll
        for (int j = 0; j < 8; j++) {
            float p00, p01, p10, p11;
            EX2(p00, fmaf(sc[j][0], cs, -m0));
            EX2(p01, fmaf(sc[j][1], cs, -m0));
            EX2(p10, fmaf(sc[j][2], cs, -m1));
            EX2(p11, fmaf(sc[j][3], cs, -m1));
            rs0 += p00 + p01;
            rs1 += p10 + p11;
            ph01[j] = packh2(p00, p01);
            ph23[j] = packh2(p10, p11);
        }
        #pragma unroll
        for (int d = 1; d < 4; d <<= 1) {
            rs0 += __shfl_xor_sync(0xffffffffu, rs0, d);
            rs1 += __shfl_xor_sync(0xffffffffu, rs1, d);
        }
        l0 = l0 * sc0 + rs0;
        l1 = l1 * sc1 + rs1;
        #pragma unroll
        for (int j = 0; j < 8; j++) {
            o[j][0] *= sc0; o[j][1] *= sc0;
            o[j][2] *= sc1; o[j][3] *= sc1;
        }

        // ---- O += P V (single fp16 term) ----
        #pragma unroll
        for (int kb = 0; kb < 4; kb++) {
            const uint32_t pa[4] = { ph01[2 * kb], ph23[2 * kb],
                                     ph01[2 * kb + 1], ph23[2 * kb + 1] };
            #pragma unroll
            for (int np = 0; np < 4; np++) {
                uint32_t vf[4];
                ldsm4t(vf, swadr(sV, kb * 16 + vKeyL, np * 2 + vChkL));
                mma_f16(o[2 * np],     pa, vf);
                mma_f16(o[2 * np + 1], pa, vf + 2);
            }
        }
    }

    // ---- epilogue: divide by l, write fp16 ----
    const float il0 = 1.0f / l0;
    const float il1 = 1.0f / l1;
    const size_t row0 = rowBase + q0 + wid * 16 + (lid >> 2);
    const size_t row1 = row0 + 8;
    const int cb = hcol + (lid & 3) * 2;
    #pragma unroll
    for (int j = 0; j < 8; j++) {
        const int col = cb + j * 8;
        *(uint32_t*)&O[row0 * 1024 + col] = packh2(o[j][0] * il0, o[j][1] * il0);
        *(uint32_t*)&O[row1 * 1024 + col] = packh2(o[j][2] * il1, o[j][3] * il1);
    }
}

// ---------------------------------------------------------------------------
// Launch
// ---------------------------------------------------------------------------
extern "C" void kernel_launch(void* const* d_in, const int* in_sizes, int n_in,
                              void* d_out, int out_size)
{
    const float* src = (const float*)d_in[0];
    const float* Wq  = (const float*)d_in[1];  const float* bq = (const float*)d_in[2];
    const float* Wk  = (const float*)d_in[3];  const float* bk = (const float*)d_in[4];
    const float* Wv  = (const float*)d_in[5];  const float* bv = (const float*)d_in[6];
    const float* Wo  = (const float*)d_in[7];  const float* bo = (const float*)d_in[8];
    const float* W1  = (const float*)d_in[9];  const float* b1 = (const float*)d_in[10];
    const float* W2  = (const float*)d_in[11]; const float* b2 = (const float*)d_in[12];
    const float* g1  = (const float*)d_in[13]; const float* be1 = (const float*)d_in[14];
    const float* g2  = (const float*)d_in[15]; const float* be2 = (const float*)d_in[16];
    float* out = (float*)d_out;

    float* x1;
    __half *a, *q, *k, *v, *h1, *whi, *wlo;
    cudaGetSymbolAddress((void**)&x1,  g_x1);
    cudaGetSymbolAddress((void**)&a,   g_a);
    cudaGetSymbolAddress((void**)&q,   g_q);
    cudaGetSymbolAddress((void**)&k,   g_k);
    cudaGetSymbolAddress((void**)&v,   g_v);
    cudaGetSymbolAddress((void**)&h1,  g_h1);
    cudaGetSymbolAddress((void**)&whi, g_whi);
    cudaGetSymbolAddress((void**)&wlo, g_wlo);

    cudaFuncSetAttribute(mm_gemm,  cudaFuncAttributeMaxDynamicSharedMemorySize, MMG_SMEM);
    cudaFuncSetAttribute(attn_mma, cudaFuncAttributeMaxDynamicSharedMemorySize, ATT_SMEM);

    const int WN = D_MODEL * D_MODEL;
    const dim3 gGemm(D_MODEL / 128, M_TOTAL / 128);  // (8, 64)
    const dim3 gAttn(SEQ / AQ, BATCH * NHEADS);      // (16, 64)
    const dim3 gWs(WN / 4 / 256, 6);

    wsplit6_kernel<<<gWs, 256>>>(Wq, Wk, Wv, Wo, W1, W2, whi, wlo);
    ln_half_kernel<<<M_TOTAL, 256>>>(src, g1, be1, a);

    mm_gemm<<<gGemm, 256, MMG_SMEM>>>(a, whi + 0 * WN, wlo + 0 * WN, bq,
                                      nullptr, nullptr, q, 0);
    mm_gemm<<<gGemm, 256, MMG_SMEM>>>(a, whi + 1 * WN, wlo + 1 * WN, bk,
                                      nullptr, nullptr, k, 0);
    mm_gemm<<<gGemm, 256, MMG_SMEM>>>(a, whi + 2 * WN, wlo + 2 * WN, bv,
                                      nullptr, nullptr, v, 0);

    attn_mma<<<gAttn, 256, ATT_SMEM>>>(q, k, v, a);

    // x1 = src + att @ Wo^T + bo   (fp32 out)
    mm_gemm<<<gGemm, 256, MMG_SMEM>>>(a, whi + 3 * WN, wlo + 3 * WN, bo,
                                      src, x1, nullptr, 0);

    // ln2(x1) -> fp16; h1 = relu(... @ W1^T + b1)
    ln_half_kernel<<<M_TOTAL, 256>>>(x1, g2, be2, a);
    mm_gemm<<<gGemm, 256, MMG_SMEM>>>(a, whi + 4 * WN, wlo + 4 * WN, b1,
                                      nullptr, nullptr, h1, 1);

    // out = x1 + h1 @ W2^T + b2
    mm_gemm<<<gGemm, 256, MMG_SMEM>>>(h1, whi + 5 * WN, wlo + 5 * WN, b2,
                                      x1, out, nullptr, 0);
}

// round 7
// speedup vs baseline: 8.9692x; 1.4819x over previous
#include <cuda_runtime.h>
#include <cuda_fp16.h>
#include <math.h>
#include <stdint.h>

#define D_MODEL 1024
#define SEQ     2048
#define BATCH   4
#define NHEADS  16
#define HDIM    64
#define M_TOTAL (BATCH * SEQ)      // 8192
#define LN_EPS  1e-5f

// ---------------------------------------------------------------------------
// Scratch buffers (allocation-free rule: __device__ globals)
// ---------------------------------------------------------------------------
__device__ float  g_x1 [M_TOTAL * D_MODEL];
__device__ __half g_a  [M_TOTAL * D_MODEL];    // activations (LN out / att out)
__device__ __half g_q  [M_TOTAL * D_MODEL];
__device__ __half g_k  [M_TOTAL * D_MODEL];
__device__ __half g_v  [M_TOTAL * D_MODEL];
__device__ __half g_h1 [M_TOTAL * D_MODEL];
__device__ __half g_wh [6 * D_MODEL * D_MODEL];

// ---------------------------------------------------------------------------
// Helpers (sm_80+ ISA: mma.sync / ldmatrix / cp.async)
// ---------------------------------------------------------------------------
__device__ __forceinline__ uint32_t smem_u32(const void* p) {
    uint32_t a;
    asm("{ .reg .u64 t; cvta.to.shared.u64 t, %1; cvt.u32.u64 %0, t; }" : "=r"(a) : "l"(p));
    return a;
}
#define CP_ASYNC16(sa, g) \
    asm volatile("cp.async.cg.shared.global [%0], [%1], 16;" :: "r"(sa), "l"(g) : "memory")
#define CP_COMMIT() asm volatile("cp.async.commit_group;" ::: "memory")
#define CP_WAIT0()  asm volatile("cp.async.wait_group 0;" ::: "memory")
#define CP_WAIT1()  asm volatile("cp.async.wait_group 1;" ::: "memory")

__device__ __forceinline__ void ldsm4(uint32_t* r, uint32_t addr) {
    asm volatile("ldmatrix.sync.aligned.m8n8.x4.shared.b16 {%0,%1,%2,%3}, [%4];"
                 : "=r"(r[0]), "=r"(r[1]), "=r"(r[2]), "=r"(r[3]) : "r"(addr));
}
__device__ __forceinline__ void ldsm4t(uint32_t* r, uint32_t addr) {
    asm volatile("ldmatrix.sync.aligned.m8n8.x4.trans.shared.b16 {%0,%1,%2,%3}, [%4];"
                 : "=r"(r[0]), "=r"(r[1]), "=r"(r[2]), "=r"(r[3]) : "r"(addr));
}
__device__ __forceinline__ void mma_f16(float* d, const uint32_t* a, const uint32_t* b) {
    asm volatile("mma.sync.aligned.m16n8k16.row.col.f32.f16.f16.f32 "
                 "{%0,%1,%2,%3}, {%4,%5,%6,%7}, {%8,%9}, {%0,%1,%2,%3};"
                 : "+f"(d[0]), "+f"(d[1]), "+f"(d[2]), "+f"(d[3])
                 : "r"(a[0]), "r"(a[1]), "r"(a[2]), "r"(a[3]), "r"(b[0]), "r"(b[1]));
}
#define EX2(d, x) asm("ex2.approx.ftz.f32 %0, %1;" : "=f"(d) : "f"(x))

__device__ __forceinline__ uint32_t packh2(float v0, float v1) {
    __half2 t = __floats2half2_rn(v0, v1);
    return *(uint32_t*)&t;
}

// ---------------------------------------------------------------------------
// All six weight conversions (fp32 -> fp16) in one launch
// ---------------------------------------------------------------------------
__global__ void __launch_bounds__(256) wconv6_kernel(
    const float* __restrict__ w0, const float* __restrict__ w1,
    const float* __restrict__ w2, const float* __restrict__ w3,
    const float* __restrict__ w4, const float* __restrict__ w5,
    __half* __restrict__ dst)
{
    const int ws = blockIdx.y;
    const float* src = (ws == 0) ? w0 : (ws == 1) ? w1 : (ws == 2) ? w2
                     : (ws == 3) ? w3 : (ws == 4) ? w4 : w5;
    const int i = blockIdx.x * 256 + threadIdx.x;
    const float4 v = ((const float4*)src)[i];
    const size_t base = (size_t)ws * (D_MODEL * D_MODEL / 2) + 2 * i;
    ((uint32_t*)dst)[base]     = packh2(v.x, v.y);
    ((uint32_t*)dst)[base + 1] = packh2(v.z, v.w);
}

// ---------------------------------------------------------------------------
// Fused LayerNorm -> single fp16
// ---------------------------------------------------------------------------
__global__ void __launch_bounds__(256) ln_half_kernel(
    const float* __restrict__ x, const float* __restrict__ g,
    const float* __restrict__ b, __half* __restrict__ y)
{
    __shared__ float red[16];
    const int row = blockIdx.x;
    const int tid = threadIdx.x;
    const float4 v = ((const float4*)(x + (size_t)row * D_MODEL))[tid];

    float s  = v.x + v.y + v.z + v.w;
    float ss = v.x * v.x + v.y * v.y + v.z * v.z + v.w * v.w;
    #pragma unroll
    for (int o = 16; o; o >>= 1) {
        s  += __shfl_xor_sync(0xffffffffu, s,  o);
        ss += __shfl_xor_sync(0xffffffffu, ss, o);
    }
    const int wid = tid >> 5;
    if ((tid & 31) == 0) { red[wid] = s; red[8 + wid] = ss; }
    __syncthreads();
    float S = 0.f, SS = 0.f;
    #pragma unroll
    for (int w = 0; w < 8; w++) { S += red[w]; SS += red[8 + w]; }
    const float mu   = S * (1.0f / D_MODEL);
    const float var  = SS * (1.0f / D_MODEL) - mu * mu;
    const float rstd = rsqrtf(var + LN_EPS);

    const float4 gv = ((const float4*)g)[tid];
    const float4 bv = ((const float4*)b)[tid];
    const float o0 = (v.x - mu) * rstd * gv.x + bv.x;
    const float o1 = (v.y - mu) * rstd * gv.y + bv.y;
    const float o2 = (v.z - mu) * rstd * gv.z + bv.z;
    const float o3 = (v.w - mu) * rstd * gv.w + bv.w;
    const size_t base = (size_t)row * (D_MODEL / 2) + tid * 2;
    ((uint32_t*)y)[base]     = packh2(o0, o1);
    ((uint32_t*)y)[base + 1] = packh2(o2, o3);
}

// ---------------------------------------------------------------------------
// fp16 GEMM: C = A * W^T + bias [+ReLU] [+res]. Single fp16 term.
// Supports fused multi-output: grid.x = 8*nOut; group g = blockIdx.x>>3
// selects bias g and output buffer g. W rows indexed by blockIdx.x*128.
// 128x128 CTA tile, BK=64, 2-stage cp.async (32KB/stage), 2 CTAs/SM.
// ---------------------------------------------------------------------------
#define TILE_B   16384                  // 128 rows x 64 fp16 x 2B
#define STAGE_B  (2 * TILE_B)           // A, W = 32KB
#define MMG_SMEM (2 * STAGE_B)          // 65536

__device__ __forceinline__ uint32_t swadr(uint32_t tbase, int row, int chunk) {
    return tbase + row * 128 + (((chunk ^ row) & 7) << 4) + ((chunk & ~7) << 4);
}

__global__ void __launch_bounds__(256, 2)
mm_gemm(const __half* __restrict__ A, const __half* __restrict__ W,
        const float* __restrict__ bias0, const float* __restrict__ bias1,
        const float* __restrict__ bias2, const float* __restrict__ res,
        float* __restrict__ Cf, __half* __restrict__ C0,
        __half* __restrict__ C1, __half* __restrict__ C2, int doRelu)
{
    extern __shared__ char smem[];
    const uint32_t sb = smem_u32(smem);
    const int tid = threadIdx.x;
    const int wid = tid >> 5;
    const int lid = tid & 31;
    const int warpM = wid >> 2;
    const int warpN = wid & 3;
    const int grp = blockIdx.x >> 3;                  // output group (0..2)
    const int cn  = (blockIdx.x & 7) * 128;           // column in output buffer
    const int bm  = blockIdx.y * 128;

    const float* bias = (grp == 0) ? bias0 : (grp == 1) ? bias1 : bias2;
    __half* Ch = (grp == 0) ? C0 : (grp == 1) ? C1 : C2;

    const __half* baseA = A + (size_t)bm * 1024;
    const __half* baseW = W + (size_t)blockIdx.x * 128 * 1024;

    // 2048 x 16B chunks per stage; 8 per thread
    #define LOAD_CHUNK(stg, k0) do {                                              \
        const uint32_t _sbase = sb + (stg) * STAGE_B;                             \
        _Pragma("unroll")                                                         \
        for (int i = 0; i < 8; i++) {                                             \
            const int tile = i >> 2;                                              \
            const int idx  = (tid + i * 256) & 1023;                              \
            const int r    = idx >> 3;                                            \
            const int c8   = idx & 7;                                             \
            const __half* gp = (tile == 0 ? baseA : baseW)                        \
                + (size_t)r * 1024 + (k0) + c8 * 8;                               \
            const uint32_t sa = _sbase + tile * TILE_B +                          \
                (uint32_t)(r * 128 + (((c8 ^ r) & 7) << 4));                      \
            CP_ASYNC16(sa, gp);                                                   \
        }                                                                         \
        CP_COMMIT();                                                              \
    } while (0)

    float acc[4][4][4];
    #pragma unroll
    for (int a = 0; a < 4; a++)
        #pragma unroll
        for (int b = 0; b < 4; b++)
            #pragma unroll
            for (int c = 0; c < 4; c++) acc[a][b][c] = 0.f;

    const int aRow = warpM * 64 + (lid & 15);
    const int aChk = lid >> 4;
    const int bRow = warpN * 32 + ((lid >= 16) ? 8 : 0) + (lid & 7);
    const int bChk = (lid >> 3) & 1;

    LOAD_CHUNK(0, 0);

    #pragma unroll 1
    for (int c = 0; c < 16; c++) {
        const int s = c & 1;
        __syncthreads();
        if (c < 15) { LOAD_CHUNK(s ^ 1, (c + 1) * 64); CP_WAIT1(); }
        else        { CP_WAIT0(); }
        __syncthreads();

        const uint32_t sA = sb + s * STAGE_B;
        const uint32_t sW = sA + TILE_B;

        #pragma unroll
        for (int s16 = 0; s16 < 4; s16++) {
            const int kc = s16 * 2;
            uint32_t Bf[4][2];
            #pragma unroll
            for (int pair = 0; pair < 2; pair++)
                ldsm4(&Bf[pair * 2][0], swadr(sW, bRow + pair * 16, kc + bChk));
            #pragma unroll
            for (int mt = 0; mt < 4; mt++) {
                uint32_t Af[4];
                ldsm4(Af, swadr(sA, aRow + mt * 16, kc + aChk));
                #pragma unroll
                for (int nt = 0; nt < 4; nt++)
                    mma_f16(acc[mt][nt], Af, Bf[nt]);
            }
        }
    }

    const int rowoff = lid >> 2;
    const int coloff = (lid & 3) * 2;
    #pragma unroll
    for (int mt = 0; mt < 4; mt++) {
        #pragma unroll
        for (int nt = 0; nt < 4; nt++) {
            const int gn = cn + warpN * 32 + nt * 8 + coloff;
            const float b0 = __ldg(&bias[gn]);
            const float b1 = __ldg(&bias[gn + 1]);
            #pragma unroll
            for (int half = 0; half < 2; half++) {
                const int gm = bm + warpM * 64 + mt * 16 + rowoff + half * 8;
                float v0 = acc[mt][nt][half * 2 + 0] + b0;
                float v1 = acc[mt][nt][half * 2 + 1] + b1;
                if (doRelu) { v0 = fmaxf(v0, 0.f); v1 = fmaxf(v1, 0.f); }
                const size_t off = (size_t)gm * 1024 + gn;
                if (res) {
                    const float2 rv = *(const float2*)&res[off];
                    v0 += rv.x; v1 += rv.y;
                }
                if (Cf) *(float2*)&Cf[off] = make_float2(v0, v1);
                else    *(uint32_t*)&Ch[off] = packh2(v0, v1);
            }
        }
    }
}

// ---------------------------------------------------------------------------
// Flash attention, single-term fp16 MMA. Per CTA: one (b,h), 128 queries,
// 8 warps x 16 rows, 64-key tiles, 3-stage cp.async. 2 CTAs/SM.
// smem: Q 16KB | 3 stages x (K 8KB + V 8KB)
// ---------------------------------------------------------------------------
#define AQ 128
#define AK 64
#define ATT_ST   16384
#define ATT_STB  16384
#define ATT_SMEM (ATT_ST + 3 * ATT_STB)   // 65536

__global__ void __launch_bounds__(256, 2) attn_mma(
    const __half* __restrict__ Q, const __half* __restrict__ K,
    const __half* __restrict__ V, __half* __restrict__ O)
{
    extern __shared__ char smem[];
    const uint32_t sb = smem_u32(smem);
    const int tid = threadIdx.x;
    const int wid = tid >> 5;
    const int lid = tid & 31;
    const int bh  = blockIdx.y;
    const int b   = bh >> 4;
    const int h   = bh & 15;
    const int q0  = blockIdx.x * AQ;
    const size_t rowBase = (size_t)b * SEQ;
    const int hcol = h * HDIM;

    // ---- Q load: 1024 chunks, 4/thread ----
    {
        #pragma unroll
        for (int i = 0; i < 4; i++) {
            const int idx = tid + i * 256;
            const int r   = idx >> 3;
            const int c8  = idx & 7;
            const __half* gp = Q + (rowBase + q0 + r) * 1024 + hcol + c8 * 8;
            const uint32_t sa = sb + (uint32_t)(r * 128 + (((c8 ^ r) & 7) << 4));
            CP_ASYNC16(sa, gp);
        }
        CP_COMMIT();
    }

    #define LOAD_KV(stg, kt) do {                                               \
        const uint32_t _sbase = sb + ATT_ST + (stg) * ATT_STB;                  \
        _Pragma("unroll")                                                       \
        for (int i = 0; i < 4; i++) {                                           \
            const int tile = i >> 1;                                            \
            const int idx  = (tid + (i & 1) * 256) & 511;                       \
            const int r    = idx >> 3;                                          \
            const int c8   = idx & 7;                                           \
            const __half* gp = (tile ? V : K)                                   \
                + (rowBase + (kt) * AK + r) * 1024 + hcol + c8 * 8;             \
            const uint32_t sa = _sbase + tile * 8192 +                          \
                (uint32_t)(r * 128 + (((c8 ^ r) & 7) << 4));                    \
            CP_ASYNC16(sa, gp);                                                 \
        }                                                                       \
        CP_COMMIT();                                                            \
    } while (0)

    LOAD_KV(0, 0);
    LOAD_KV(1, 1);
    CP_WAIT1();
    __syncthreads();

    uint32_t Qf[4][4];
    {
        const int r = wid * 16 + (lid & 15);
        const int ck = lid >> 4;
        #pragma unroll
        for (int t = 0; t < 4; t++) ldsm4(Qf[t], swadr(sb, r, 2 * t + ck));
    }

    float o[8][4];
    #pragma unroll
    for (int j = 0; j < 8; j++)
        #pragma unroll
        for (int e = 0; e < 4; e++) o[j][e] = 0.f;
    float m0 = -INFINITY, m1 = -INFINITY, l0 = 0.f, l1 = 0.f;
    const float cs = 0.125f * 1.4426950408889634f;

    const int kRowL = ((lid >= 16) ? 8 : 0) + (lid & 7);
    const int kChkL = (lid >> 3) & 1;
    const int vT    = lid >> 3;
    const int vKeyL = ((vT & 1) << 3) + (lid & 7);
    const int vChkL = vT >> 1;

    #pragma unroll 1
    for (int kt = 0; kt < SEQ / AK; kt++) {
        if (kt > 0) {
            if (kt == SEQ / AK - 1) CP_WAIT0(); else CP_WAIT1();
            __syncthreads();
        }
        if (kt + 2 < SEQ / AK) LOAD_KV((kt + 2) % 3, kt + 2);

        const uint32_t sK = sb + ATT_ST + (kt % 3) * ATT_STB;
        const uint32_t sV = sK + 8192;

        float sc[8][4];
        #pragma unroll
        for (int j = 0; j < 8; j++)
            #pragma unroll
            for (int e = 0; e < 4; e++) sc[j][e] = 0.f;

        #pragma unroll
        for (int t = 0; t < 4; t++) {
            #pragma unroll
            for (int kp = 0; kp < 4; kp++) {
                uint32_t kf[4];
                ldsm4(kf, swadr(sK, kp * 16 + kRowL, 2 * t + kChkL));
                mma_f16(sc[2 * kp],     Qf[t], kf);
                mma_f16(sc[2 * kp + 1], Qf[t], kf + 2);
            }
        }

        float mx0 = -INFINITY, mx1 = -INFINITY;
        #pragma unroll
        for (int j = 0; j < 8; j++) {
            mx0 = fmaxf(mx0, fmaxf(sc[j][0], sc[j][1]));
            mx1 = fmaxf(mx1, fmaxf(sc[j][2], sc[j][3]));
        }
        mx0 *= cs; mx1 *= cs;
        #pragma unroll
        for (int d = 1; d < 4; d <<= 1) {
            mx0 = fmaxf(mx0, __shfl_xor_sync(0xffffffffu, mx0, d));
            mx1 = fmaxf(mx1, __shfl_xor_sync(0xffffffffu, mx1, d));
        }
        const float m0n = fmaxf(m0, mx0);
        const float m1n = fmaxf(m1, mx1);
        float sc0, sc1;
        EX2(sc0, m0 - m0n);
        EX2(sc1, m1 - m1n);
        m0 = m0n; m1 = m1n;

        float rs0 = 0.f, rs1 = 0.f;
        uint32_t ph01[8], ph23[8];
        #pragma unroll
        for (int j = 0; j < 8; j++) {
            float p00, p01, p10, p11;
            EX2(p00, fmaf(sc[j][0], cs, -m0));
            EX2(p01, fmaf(sc[j][1], cs, -m0));
            EX2(p10, fmaf(sc[j][2], cs, -m1));
            EX2(p11, fmaf(sc[j][3], cs, -m1));
            rs0 += p00 + p01;
            rs1 += p10 + p11;
            ph01[j] = packh2(p00, p01);
            ph23[j] = packh2(p10, p11);
        }
        #pragma unroll
        for (int d = 1; d < 4; d <<= 1) {
            rs0 += __shfl_xor_sync(0xffffffffu, rs0, d);
            rs1 += __shfl_xor_sync(0xffffffffu, rs1, d);
        }
        l0 = l0 * sc0 + rs0;
        l1 = l1 * sc1 + rs1;
        #pragma unroll
        for (int j = 0; j < 8; j++) {
            o[j][0] *= sc0; o[j][1] *= sc0;
            o[j][2] *= sc1; o[j][3] *= sc1;
        }

        #pragma unroll
        for (int kb = 0; kb < 4; kb++) {
            const uint32_t pa[4] = { ph01[2 * kb], ph23[2 * kb],
                                     ph01[2 * kb + 1], ph23[2 * kb + 1] };
            #pragma unroll
            for (int np = 0; np < 4; np++) {
                uint32_t vf[4];
                ldsm4t(vf, swadr(sV, kb * 16 + vKeyL, np * 2 + vChkL));
                mma_f16(o[2 * np],     pa, vf);
                mma_f16(o[2 * np + 1], pa, vf + 2);
            }
        }
    }

    const float il0 = 1.0f / l0;
    const float il1 = 1.0f / l1;
    const size_t row0 = rowBase + q0 + wid * 16 + (lid >> 2);
    const size_t row1 = row0 + 8;
    const int cb = hcol + (lid & 3) * 2;
    #pragma unroll
    for (int j = 0; j < 8; j++) {
        const int col = cb + j * 8;
        *(uint32_t*)&O[row0 * 1024 + col] = packh2(o[j][0] * il0, o[j][1] * il0);
        *(uint32_t*)&O[row1 * 1024 + col] = packh2(o[j][2] * il1, o[j][3] * il1);
    }
}

// ---------------------------------------------------------------------------
// Launch
// ---------------------------------------------------------------------------
extern "C" void kernel_launch(void* const* d_in, const int* in_sizes, int n_in,
                              void* d_out, int out_size)
{
    const float* src = (const float*)d_in[0];
    const float* Wq  = (const float*)d_in[1];  const float* bq = (const float*)d_in[2];
    const float* Wk  = (const float*)d_in[3];  const float* bk = (const float*)d_in[4];
    const float* Wv  = (const float*)d_in[5];  const float* bv = (const float*)d_in[6];
    const float* Wo  = (const float*)d_in[7];  const float* bo = (const float*)d_in[8];
    const float* W1  = (const float*)d_in[9];  const float* b1 = (const float*)d_in[10];
    const float* W2  = (const float*)d_in[11]; const float* b2 = (const float*)d_in[12];
    const float* g1  = (const float*)d_in[13]; const float* be1 = (const float*)d_in[14];
    const float* g2  = (const float*)d_in[15]; const float* be2 = (const float*)d_in[16];
    float* out = (float*)d_out;

    float* x1;
    __half *a, *q, *k, *v, *h1, *wh;
    cudaGetSymbolAddress((void**)&x1, g_x1);
    cudaGetSymbolAddress((void**)&a,  g_a);
    cudaGetSymbolAddress((void**)&q,  g_q);
    cudaGetSymbolAddress((void**)&k,  g_k);
    cudaGetSymbolAddress((void**)&v,  g_v);
    cudaGetSymbolAddress((void**)&h1, g_h1);
    cudaGetSymbolAddress((void**)&wh, g_wh);

    cudaFuncSetAttribute(mm_gemm,  cudaFuncAttributeMaxDynamicSharedMemorySize, MMG_SMEM);
    cudaFuncSetAttribute(attn_mma, cudaFuncAttributeMaxDynamicSharedMemorySize, ATT_SMEM);

    const int WN = D_MODEL * D_MODEL;
    const dim3 gQKV(24, M_TOTAL / 128);              // fused: N = 3072
    const dim3 gGemm(8, M_TOTAL / 128);              // single: N = 1024
    const dim3 gAttn(SEQ / AQ, BATCH * NHEADS);      // (16, 64)
    const dim3 gWs(WN / 4 / 256, 6);

    wconv6_kernel<<<gWs, 256>>>(Wq, Wk, Wv, Wo, W1, W2, wh);
    ln_half_kernel<<<M_TOTAL, 256>>>(src, g1, be1, a);

    // fused Q/K/V projection: W rows 0..3071 = [Wq; Wk; Wv]
    mm_gemm<<<gQKV, 256, MMG_SMEM>>>(a, wh, bq, bk, bv,
                                     nullptr, nullptr, q, k, v, 0);

    attn_mma<<<gAttn, 256, ATT_SMEM>>>(q, k, v, a);

    // x1 = src + att @ Wo^T + bo   (fp32 out)
    mm_gemm<<<gGemm, 256, MMG_SMEM>>>(a, wh + 3 * WN, bo, bo, bo,
                                      src, x1, nullptr, nullptr, nullptr, 0);

    // ln2(x1) -> fp16; h1 = relu(... @ W1^T + b1)
    ln_half_kernel<<<M_TOTAL, 256>>>(x1, g2, be2, a);
    mm_gemm<<<gGemm, 256, MMG_SMEM>>>(a, wh + 4 * WN, b1, b1, b1,
                                      nullptr, nullptr, h1, nullptr, nullptr, 1);

    // out = x1 + h1 @ W2^T + b2
    mm_gemm<<<gGemm, 256, MMG_SMEM>>>(h1, wh + 5 * WN, b2, b2, b2,
                                      x1, out, nullptr, nullptr, nullptr, 0);
}

// round 8
// speedup vs baseline: 9.3589x; 1.0434x over previous
#include <cuda_runtime.h>
#include <cuda_fp16.h>
#include <math.h>
#include <stdint.h>

#define D_MODEL 1024
#define SEQ     2048
#define BATCH   4
#define NHEADS  16
#define HDIM    64
#define M_TOTAL (BATCH * SEQ)      // 8192
#define LN_EPS  1e-5f

// ---------------------------------------------------------------------------
// Scratch buffers (allocation-free rule: __device__ globals)
// ---------------------------------------------------------------------------
__device__ float  g_x1 [M_TOTAL * D_MODEL];
__device__ __half g_a  [M_TOTAL * D_MODEL];
__device__ __half g_q  [M_TOTAL * D_MODEL];
__device__ __half g_k  [M_TOTAL * D_MODEL];
__device__ __half g_v  [M_TOTAL * D_MODEL];
__device__ __half g_h1 [M_TOTAL * D_MODEL];
__device__ __half g_wh [6 * D_MODEL * D_MODEL];

// ---------------------------------------------------------------------------
// Helpers (sm_80+ ISA: mma.sync / ldmatrix / cp.async)
// ---------------------------------------------------------------------------
__device__ __forceinline__ uint32_t smem_u32(const void* p) {
    uint32_t a;
    asm("{ .reg .u64 t; cvta.to.shared.u64 t, %1; cvt.u32.u64 %0, t; }" : "=r"(a) : "l"(p));
    return a;
}
#define CP_ASYNC16(sa, g) \
    asm volatile("cp.async.cg.shared.global [%0], [%1], 16;" :: "r"(sa), "l"(g) : "memory")
#define CP_COMMIT() asm volatile("cp.async.commit_group;" ::: "memory")
#define CP_WAIT0()  asm volatile("cp.async.wait_group 0;" ::: "memory")
#define CP_WAIT1()  asm volatile("cp.async.wait_group 1;" ::: "memory")

__device__ __forceinline__ void ldsm4(uint32_t* r, uint32_t addr) {
    asm volatile("ldmatrix.sync.aligned.m8n8.x4.shared.b16 {%0,%1,%2,%3}, [%4];"
                 : "=r"(r[0]), "=r"(r[1]), "=r"(r[2]), "=r"(r[3]) : "r"(addr));
}
__device__ __forceinline__ void ldsm4t(uint32_t* r, uint32_t addr) {
    asm volatile("ldmatrix.sync.aligned.m8n8.x4.trans.shared.b16 {%0,%1,%2,%3}, [%4];"
                 : "=r"(r[0]), "=r"(r[1]), "=r"(r[2]), "=r"(r[3]) : "r"(addr));
}
__device__ __forceinline__ void mma_f16(float* d, const uint32_t* a, const uint32_t* b) {
    asm volatile("mma.sync.aligned.m16n8k16.row.col.f32.f16.f16.f32 "
                 "{%0,%1,%2,%3}, {%4,%5,%6,%7}, {%8,%9}, {%0,%1,%2,%3};"
                 : "+f"(d[0]), "+f"(d[1]), "+f"(d[2]), "+f"(d[3])
                 : "r"(a[0]), "r"(a[1]), "r"(a[2]), "r"(a[3]), "r"(b[0]), "r"(b[1]));
}
#define EX2(d, x) asm("ex2.approx.ftz.f32 %0, %1;" : "=f"(d) : "f"(x))

__device__ __forceinline__ uint32_t packh2(float v0, float v1) {
    __half2 t = __floats2half2_rn(v0, v1);
    return *(uint32_t*)&t;
}

// ---------------------------------------------------------------------------
// All six weight conversions (fp32 -> fp16) in one launch
// ---------------------------------------------------------------------------
__global__ void __launch_bounds__(256) wconv6_kernel(
    const float* __restrict__ w0, const float* __restrict__ w1,
    const float* __restrict__ w2, const float* __restrict__ w3,
    const float* __restrict__ w4, const float* __restrict__ w5,
    __half* __restrict__ dst)
{
    const int ws = blockIdx.y;
    const float* src = (ws == 0) ? w0 : (ws == 1) ? w1 : (ws == 2) ? w2
                     : (ws == 3) ? w3 : (ws == 4) ? w4 : w5;
    const int i = blockIdx.x * 256 + threadIdx.x;
    const float4 v = ((const float4*)src)[i];
    const size_t base = (size_t)ws * (D_MODEL * D_MODEL / 2) + 2 * i;
    ((uint32_t*)dst)[base]     = packh2(v.x, v.y);
    ((uint32_t*)dst)[base + 1] = packh2(v.z, v.w);
}

// ---------------------------------------------------------------------------
// Fused LayerNorm -> single fp16
// ---------------------------------------------------------------------------
__global__ void __launch_bounds__(256) ln_half_kernel(
    const float* __restrict__ x, const float* __restrict__ g,
    const float* __restrict__ b, __half* __restrict__ y)
{
    __shared__ float red[16];
    const int row = blockIdx.x;
    const int tid = threadIdx.x;
    const float4 v = ((const float4*)(x + (size_t)row * D_MODEL))[tid];

    float s  = v.x + v.y + v.z + v.w;
    float ss = v.x * v.x + v.y * v.y + v.z * v.z + v.w * v.w;
    #pragma unroll
    for (int o = 16; o; o >>= 1) {
        s  += __shfl_xor_sync(0xffffffffu, s,  o);
        ss += __shfl_xor_sync(0xffffffffu, ss, o);
    }
    const int wid = tid >> 5;
    if ((tid & 31) == 0) { red[wid] = s; red[8 + wid] = ss; }
    __syncthreads();
    float S = 0.f, SS = 0.f;
    #pragma unroll
    for (int w = 0; w < 8; w++) { S += red[w]; SS += red[8 + w]; }
    const float mu   = S * (1.0f / D_MODEL);
    const float var  = SS * (1.0f / D_MODEL) - mu * mu;
    const float rstd = rsqrtf(var + LN_EPS);

    const float4 gv = ((const float4*)g)[tid];
    const float4 bv = ((const float4*)b)[tid];
    const float o0 = (v.x - mu) * rstd * gv.x + bv.x;
    const float o1 = (v.y - mu) * rstd * gv.y + bv.y;
    const float o2 = (v.z - mu) * rstd * gv.z + bv.z;
    const float o3 = (v.w - mu) * rstd * gv.w + bv.w;
    const size_t base = (size_t)row * (D_MODEL / 2) + tid * 2;
    ((uint32_t*)y)[base]     = packh2(o0, o1);
    ((uint32_t*)y)[base + 1] = packh2(o2, o3);
}

// ---------------------------------------------------------------------------
// fp16 GEMM (unchanged from round 7)
// ---------------------------------------------------------------------------
#define TILE_B   16384
#define STAGE_B  (2 * TILE_B)
#define MMG_SMEM (2 * STAGE_B)

__device__ __forceinline__ uint32_t swadr(uint32_t tbase, int row, int chunk) {
    return tbase + row * 128 + (((chunk ^ row) & 7) << 4) + ((chunk & ~7) << 4);
}

__global__ void __launch_bounds__(256, 2)
mm_gemm(const __half* __restrict__ A, const __half* __restrict__ W,
        const float* __restrict__ bias0, const float* __restrict__ bias1,
        const float* __restrict__ bias2, const float* __restrict__ res,
        float* __restrict__ Cf, __half* __restrict__ C0,
        __half* __restrict__ C1, __half* __restrict__ C2, int doRelu)
{
    extern __shared__ char smem[];
    const uint32_t sb = smem_u32(smem);
    const int tid = threadIdx.x;
    const int wid = tid >> 5;
    const int lid = tid & 31;
    const int warpM = wid >> 2;
    const int warpN = wid & 3;
    const int grp = blockIdx.x >> 3;
    const int cn  = (blockIdx.x & 7) * 128;
    const int bm  = blockIdx.y * 128;

    const float* bias = (grp == 0) ? bias0 : (grp == 1) ? bias1 : bias2;
    __half* Ch = (grp == 0) ? C0 : (grp == 1) ? C1 : C2;

    const __half* baseA = A + (size_t)bm * 1024;
    const __half* baseW = W + (size_t)blockIdx.x * 128 * 1024;

    #define LOAD_CHUNK(stg, k0) do {                                              \
        const uint32_t _sbase = sb + (stg) * STAGE_B;                             \
        _Pragma("unroll")                                                         \
        for (int i = 0; i < 8; i++) {                                             \
            const int tile = i >> 2;                                              \
            const int idx  = (tid + i * 256) & 1023;                              \
            const int r    = idx >> 3;                                            \
            const int c8   = idx & 7;                                             \
            const __half* gp = (tile == 0 ? baseA : baseW)                        \
                + (size_t)r * 1024 + (k0) + c8 * 8;                               \
            const uint32_t sa = _sbase + tile * TILE_B +                          \
                (uint32_t)(r * 128 + (((c8 ^ r) & 7) << 4));                      \
            CP_ASYNC16(sa, gp);                                                   \
        }                                                                         \
        CP_COMMIT();                                                              \
    } while (0)

    float acc[4][4][4];
    #pragma unroll
    for (int a = 0; a < 4; a++)
        #pragma unroll
        for (int b = 0; b < 4; b++)
            #pragma unroll
            for (int c = 0; c < 4; c++) acc[a][b][c] = 0.f;

    const int aRow = warpM * 64 + (lid & 15);
    const int aChk = lid >> 4;
    const int bRow = warpN * 32 + ((lid >= 16) ? 8 : 0) + (lid & 7);
    const int bChk = (lid >> 3) & 1;

    LOAD_CHUNK(0, 0);

    #pragma unroll 1
    for (int c = 0; c < 16; c++) {
        const int s = c & 1;
        __syncthreads();
        if (c < 15) { LOAD_CHUNK(s ^ 1, (c + 1) * 64); CP_WAIT1(); }
        else        { CP_WAIT0(); }
        __syncthreads();

        const uint32_t sA = sb + s * STAGE_B;
        const uint32_t sW = sA + TILE_B;

        #pragma unroll
        for (int s16 = 0; s16 < 4; s16++) {
            const int kc = s16 * 2;
            uint32_t Bf[4][2];
            #pragma unroll
            for (int pair = 0; pair < 2; pair++)
                ldsm4(&Bf[pair * 2][0], swadr(sW, bRow + pair * 16, kc + bChk));
            #pragma unroll
            for (int mt = 0; mt < 4; mt++) {
                uint32_t Af[4];
                ldsm4(Af, swadr(sA, aRow + mt * 16, kc + aChk));
                #pragma unroll
                for (int nt = 0; nt < 4; nt++)
                    mma_f16(acc[mt][nt], Af, Bf[nt]);
            }
        }
    }

    const int rowoff = lid >> 2;
    const int coloff = (lid & 3) * 2;
    #pragma unroll
    for (int mt = 0; mt < 4; mt++) {
        #pragma unroll
        for (int nt = 0; nt < 4; nt++) {
            const int gn = cn + warpN * 32 + nt * 8 + coloff;
            const float b0 = __ldg(&bias[gn]);
            const float b1 = __ldg(&bias[gn + 1]);
            #pragma unroll
            for (int half = 0; half < 2; half++) {
                const int gm = bm + warpM * 64 + mt * 16 + rowoff + half * 8;
                float v0 = acc[mt][nt][half * 2 + 0] + b0;
                float v1 = acc[mt][nt][half * 2 + 1] + b1;
                if (doRelu) { v0 = fmaxf(v0, 0.f); v1 = fmaxf(v1, 0.f); }
                const size_t off = (size_t)gm * 1024 + gn;
                if (res) {
                    const float2 rv = *(const float2*)&res[off];
                    v0 += rv.x; v1 += rv.y;
                }
                if (Cf) *(float2*)&Cf[off] = make_float2(v0, v1);
                else    *(uint32_t*)&Ch[off] = packh2(v0, v1);
            }
        }
    }
}

// ---------------------------------------------------------------------------
// Flash attention v2: 4 warps x 32 query rows (2 row-tiles of 16), 128 thr.
// Halves ldsm traffic per query vs 8-warp version (K/V frags are loaded
// per-warp; fewer warps -> less redundancy). 3-stage cp.async KV pipeline.
// smem: Q 16KB | 3 stages x (K 8KB + V 8KB) = 64KB; 2 CTAs/SM.
// ---------------------------------------------------------------------------
#define AQ 128
#define AK 64
#define ATT_ST   16384
#define ATT_STB  16384
#define ATT_SMEM (ATT_ST + 3 * ATT_STB)   // 65536

struct SoftState { float m0, m1, l0, l1; };

__device__ __forceinline__ void softmax_update(
    float sc[8][4], SoftState& st, float o[8][4],
    uint32_t* ph01, uint32_t* ph23, float cs)
{
    float mx0 = -INFINITY, mx1 = -INFINITY;
    #pragma unroll
    for (int j = 0; j < 8; j++) {
        mx0 = fmaxf(mx0, fmaxf(sc[j][0], sc[j][1]));
        mx1 = fmaxf(mx1, fmaxf(sc[j][2], sc[j][3]));
    }
    mx0 *= cs; mx1 *= cs;
    #pragma unroll
    for (int d = 1; d < 4; d <<= 1) {
        mx0 = fmaxf(mx0, __shfl_xor_sync(0xffffffffu, mx0, d));
        mx1 = fmaxf(mx1, __shfl_xor_sync(0xffffffffu, mx1, d));
    }
    const float m0n = fmaxf(st.m0, mx0);
    const float m1n = fmaxf(st.m1, mx1);
    float sc0, sc1;
    EX2(sc0, st.m0 - m0n);
    EX2(sc1, st.m1 - m1n);
    st.m0 = m0n; st.m1 = m1n;

    float rs0 = 0.f, rs1 = 0.f;
    #pragma unroll
    for (int j = 0; j < 8; j++) {
        float p00, p01, p10, p11;
        EX2(p00, fmaf(sc[j][0], cs, -st.m0));
        EX2(p01, fmaf(sc[j][1], cs, -st.m0));
        EX2(p10, fmaf(sc[j][2], cs, -st.m1));
        EX2(p11, fmaf(sc[j][3], cs, -st.m1));
        rs0 += p00 + p01;
        rs1 += p10 + p11;
        ph01[j] = packh2(p00, p01);
        ph23[j] = packh2(p10, p11);
    }
    #pragma unroll
    for (int d = 1; d < 4; d <<= 1) {
        rs0 += __shfl_xor_sync(0xffffffffu, rs0, d);
        rs1 += __shfl_xor_sync(0xffffffffu, rs1, d);
    }
    st.l0 = st.l0 * sc0 + rs0;
    st.l1 = st.l1 * sc1 + rs1;
    #pragma unroll
    for (int j = 0; j < 8; j++) {
        o[j][0] *= sc0; o[j][1] *= sc0;
        o[j][2] *= sc1; o[j][3] *= sc1;
    }
}

__global__ void __launch_bounds__(128, 2) attn_mma(
    const __half* __restrict__ Q, const __half* __restrict__ K,
    const __half* __restrict__ V, __half* __restrict__ O)
{
    extern __shared__ char smem[];
    const uint32_t sb = smem_u32(smem);
    const int tid = threadIdx.x;
    const int wid = tid >> 5;            // 0..3; warp owns 32 query rows
    const int lid = tid & 31;
    const int bh  = blockIdx.y;
    const int b   = bh >> 4;
    const int h   = bh & 15;
    const int q0  = blockIdx.x * AQ;
    const size_t rowBase = (size_t)b * SEQ;
    const int hcol = h * HDIM;

    // ---- Q load: 1024 chunks, 8/thread ----
    {
        #pragma unroll
        for (int i = 0; i < 8; i++) {
            const int idx = tid + i * 128;
            const int r   = idx >> 3;
            const int c8  = idx & 7;
            const __half* gp = Q + (rowBase + q0 + r) * 1024 + hcol + c8 * 8;
            const uint32_t sa = sb + (uint32_t)(r * 128 + (((c8 ^ r) & 7) << 4));
            CP_ASYNC16(sa, gp);
        }
        CP_COMMIT();
    }

    #define LOAD_KV(stg, kt) do {                                               \
        const uint32_t _sbase = sb + ATT_ST + (stg) * ATT_STB;                  \
        _Pragma("unroll")                                                       \
        for (int i = 0; i < 8; i++) {                                           \
            const int tile = i >> 2;                                            \
            const int idx  = (tid + (i & 3) * 128) & 511;                       \
            const int r    = idx >> 3;                                          \
            const int c8   = idx & 7;                                           \
            const __half* gp = (tile ? V : K)                                   \
                + (rowBase + (kt) * AK + r) * 1024 + hcol + c8 * 8;             \
            const uint32_t sa = _sbase + tile * 8192 +                          \
                (uint32_t)(r * 128 + (((c8 ^ r) & 7) << 4));                    \
            CP_ASYNC16(sa, gp);                                                 \
        }                                                                       \
        CP_COMMIT();                                                            \
    } while (0)

    LOAD_KV(0, 0);
    LOAD_KV(1, 1);
    CP_WAIT1();
    __syncthreads();

    // ---- persistent Q fragments: 2 row-tiles x 4 k-chunks ----
    uint32_t Qf0[4][4], Qf1[4][4];
    {
        const int r0 = wid * 32 + (lid & 15);
        const int ck = lid >> 4;
        #pragma unroll
        for (int t = 0; t < 4; t++) {
            ldsm4(Qf0[t], swadr(sb, r0,      2 * t + ck));
            ldsm4(Qf1[t], swadr(sb, r0 + 16, 2 * t + ck));
        }
    }

    float o0[8][4], o1[8][4];
    #pragma unroll
    for (int j = 0; j < 8; j++)
        #pragma unroll
        for (int e = 0; e < 4; e++) { o0[j][e] = 0.f; o1[j][e] = 0.f; }
    SoftState st0 = { -INFINITY, -INFINITY, 0.f, 0.f };
    SoftState st1 = { -INFINITY, -INFINITY, 0.f, 0.f };
    const float cs = 0.125f * 1.4426950408889634f;

    const int kRowL = ((lid >= 16) ? 8 : 0) + (lid & 7);
    const int kChkL = (lid >> 3) & 1;
    const int vT    = lid >> 3;
    const int vKeyL = ((vT & 1) << 3) + (lid & 7);
    const int vChkL = vT >> 1;

    #pragma unroll 1
    for (int kt = 0; kt < SEQ / AK; kt++) {
        if (kt > 0) {
            if (kt == SEQ / AK - 1) CP_WAIT0(); else CP_WAIT1();
            __syncthreads();
        }
        if (kt + 2 < SEQ / AK) LOAD_KV((kt + 2) % 3, kt + 2);

        const uint32_t sK = sb + ATT_ST + (kt % 3) * ATT_STB;
        const uint32_t sV = sK + 8192;

        // ---- S = Q K^T for both row-tiles, K frags loaded once ----
        float sc0[8][4], sc1[8][4];
        #pragma unroll
        for (int j = 0; j < 8; j++)
            #pragma unroll
            for (int e = 0; e < 4; e++) { sc0[j][e] = 0.f; sc1[j][e] = 0.f; }

        #pragma unroll
        for (int t = 0; t < 4; t++) {
            #pragma unroll
            for (int kp = 0; kp < 4; kp++) {
                uint32_t kf[4];
                ldsm4(kf, swadr(sK, kp * 16 + kRowL, 2 * t + kChkL));
                mma_f16(sc0[2 * kp],     Qf0[t], kf);
                mma_f16(sc0[2 * kp + 1], Qf0[t], kf + 2);
                mma_f16(sc1[2 * kp],     Qf1[t], kf);
                mma_f16(sc1[2 * kp + 1], Qf1[t], kf + 2);
            }
        }

        // ---- online softmax per row-tile ----
        uint32_t p0h01[8], p0h23[8], p1h01[8], p1h23[8];
        softmax_update(sc0, st0, o0, p0h01, p0h23, cs);
        softmax_update(sc1, st1, o1, p1h01, p1h23, cs);

        // ---- O += P V, V frags loaded once ----
        #pragma unroll
        for (int kb = 0; kb < 4; kb++) {
            const uint32_t pa0[4] = { p0h01[2 * kb], p0h23[2 * kb],
                                      p0h01[2 * kb + 1], p0h23[2 * kb + 1] };
            const uint32_t pa1[4] = { p1h01[2 * kb], p1h23[2 * kb],
                                      p1h01[2 * kb + 1], p1h23[2 * kb + 1] };
            #pragma unroll
            for (int np = 0; np < 4; np++) {
                uint32_t vf[4];
                ldsm4t(vf, swadr(sV, kb * 16 + vKeyL, np * 2 + vChkL));
                mma_f16(o0[2 * np],     pa0, vf);
                mma_f16(o0[2 * np + 1], pa0, vf + 2);
                mma_f16(o1[2 * np],     pa1, vf);
                mma_f16(o1[2 * np + 1], pa1, vf + 2);
            }
        }
    }

    // ---- epilogue: both row-tiles ----
    const int cb = hcol + (lid & 3) * 2;
    {
        const float il0 = 1.0f / st0.l0;
        const float il1 = 1.0f / st0.l1;
        const size_t row0 = rowBase + q0 + wid * 32 + (lid >> 2);
        const size_t row1 = row0 + 8;
        #pragma unroll
        for (int j = 0; j < 8; j++) {
            const int col = cb + j * 8;
            *(uint32_t*)&O[row0 * 1024 + col] = packh2(o0[j][0] * il0, o0[j][1] * il0);
            *(uint32_t*)&O[row1 * 1024 + col] = packh2(o0[j][2] * il1, o0[j][3] * il1);
        }
    }
    {
        const float il0 = 1.0f / st1.l0;
        const float il1 = 1.0f / st1.l1;
        const size_t row0 = rowBase + q0 + wid * 32 + 16 + (lid >> 2);
        const size_t row1 = row0 + 8;
        #pragma unroll
        for (int j = 0; j < 8; j++) {
            const int col = cb + j * 8;
            *(uint32_t*)&O[row0 * 1024 + col] = packh2(o1[j][0] * il0, o1[j][1] * il0);
            *(uint32_t*)&O[row1 * 1024 + col] = packh2(o1[j][2] * il1, o1[j][3] * il1);
        }
    }
}

// ---------------------------------------------------------------------------
// Launch
// ---------------------------------------------------------------------------
extern "C" void kernel_launch(void* const* d_in, const int* in_sizes, int n_in,
                              void* d_out, int out_size)
{
    const float* src = (const float*)d_in[0];
    const float* Wq  = (const float*)d_in[1];  const float* bq = (const float*)d_in[2];
    const float* Wk  = (const float*)d_in[3];  const float* bk = (const float*)d_in[4];
    const float* Wv  = (const float*)d_in[5];  const float* bv = (const float*)d_in[6];
    const float* Wo  = (const float*)d_in[7];  const float* bo = (const float*)d_in[8];
    const float* W1  = (const float*)d_in[9];  const float* b1 = (const float*)d_in[10];
    const float* W2  = (const float*)d_in[11]; const float* b2 = (const float*)d_in[12];
    const float* g1  = (const float*)d_in[13]; const float* be1 = (const float*)d_in[14];
    const float* g2  = (const float*)d_in[15]; const float* be2 = (const float*)d_in[16];
    float* out = (float*)d_out;

    float* x1;
    __half *a, *q, *k, *v, *h1, *wh;
    cudaGetSymbolAddress((void**)&x1, g_x1);
    cudaGetSymbolAddress((void**)&a,  g_a);
    cudaGetSymbolAddress((void**)&q,  g_q);
    cudaGetSymbolAddress((void**)&k,  g_k);
    cudaGetSymbolAddress((void**)&v,  g_v);
    cudaGetSymbolAddress((void**)&h1, g_h1);
    cudaGetSymbolAddress((void**)&wh, g_wh);

    cudaFuncSetAttribute(mm_gemm,  cudaFuncAttributeMaxDynamicSharedMemorySize, MMG_SMEM);
    cudaFuncSetAttribute(attn_mma, cudaFuncAttributeMaxDynamicSharedMemorySize, ATT_SMEM);

    const int WN = D_MODEL * D_MODEL;
    const dim3 gQKV(24, M_TOTAL / 128);
    const dim3 gGemm(8, M_TOTAL / 128);
    const dim3 gAttn(SEQ / AQ, BATCH * NHEADS);
    const dim3 gWs(WN / 4 / 256, 6);

    wconv6_kernel<<<gWs, 256>>>(Wq, Wk, Wv, Wo, W1, W2, wh);
    ln_half_kernel<<<M_TOTAL, 256>>>(src, g1, be1, a);

    mm_gemm<<<gQKV, 256, MMG_SMEM>>>(a, wh, bq, bk, bv,
                                     nullptr, nullptr, q, k, v, 0);

    attn_mma<<<gAttn, 128, ATT_SMEM>>>(q, k, v, a);

    mm_gemm<<<gGemm, 256, MMG_SMEM>>>(a, wh + 3 * WN, bo, bo, bo,
                                      src, x1, nullptr, nullptr, nullptr, 0);

    ln_half_kernel<<<M_TOTAL, 256>>>(x1, g2, be2, a);
    mm_gemm<<<gGemm, 256, MMG_SMEM>>>(a, wh + 4 * WN, b1, b1, b1,
                                      nullptr, nullptr, h1, nullptr, nullptr, 1);

    mm_gemm<<<gGemm, 256, MMG_SMEM>>>(h1, wh + 5 * WN, b2, b2, b2,
                                      x1, out, nullptr, nullptr, nullptr, 0);
}